// round 5
// baseline (speedup 1.0000x reference)
#include <cuda_runtime.h>
#include <math.h>

// ---------------- problem constants ----------------
#define BATCH   16
#define CDIM    512
#define HWDIM   1024            // H*W = 32*32
#define NGROUPS 32
#define CPG     (CDIM / NGROUPS)   // 16 channels per group
#define NH      8
#define DH      64                  // head dim
#define C3      (3 * CDIM)          // 1536
#define EPSV    1e-5f

// scale = C ** -0.5 (full dim, per reference)
#define ATTN_SCALE 0.044194173824159216f

typedef unsigned long long u64;

// ---------------- packed f32x2 helpers (sm_103a) ----------------
__device__ __forceinline__ void ffma2(u64& d, u64 a, u64 b) {
    asm("fma.rn.f32x2 %0, %1, %2, %0;" : "+l"(d) : "l"(a), "l"(b));
}
__device__ __forceinline__ u64 fmul2(u64 a, u64 b) {
    u64 r; asm("mul.rn.f32x2 %0, %1, %2;" : "=l"(r) : "l"(a), "l"(b)); return r;
}
__device__ __forceinline__ u64 pk2(float lo, float hi) {
    u64 r; asm("mov.b64 %0, {%1, %2};" : "=l"(r) : "f"(lo), "f"(hi)); return r;
}
__device__ __forceinline__ float2 upk2(u64 p) {
    float2 v; asm("mov.b64 {%0, %1}, %2;" : "=f"(v.x), "=f"(v.y) : "l"(p)); return v;
}

// ---------------- scratch (device globals: alloc-free rule) ----------------
__device__ float g_h[BATCH * CDIM * HWDIM];    // groupnorm output   (B, C, HW)
__device__ float g_qkv[BATCH * C3 * HWDIM];    // qkv projection     (B, 3C, HW)
__device__ float g_ao[BATCH * CDIM * HWDIM];   // attn out, scrambled(B, C, HW)

// ============================================================
// 1) GroupNorm: one block per (batch, group).
// ============================================================
__global__ __launch_bounds__(256)
void groupnorm_kernel(const float* __restrict__ x,
                      const float* __restrict__ gamma,
                      const float* __restrict__ beta)
{
    const int bg = blockIdx.x;
    const int b = bg / NGROUPS, g = bg % NGROUPS;
    const int t = threadIdx.x;
    const float* xp = x   + (size_t)(b * CDIM + g * CPG) * HWDIM;
    float*       hp = g_h + (size_t)(b * CDIM + g * CPG) * HWDIM;

    float4 v[16];
    float s = 0.f, ss = 0.f;
#pragma unroll
    for (int i = 0; i < 16; i++) {
        v[i] = reinterpret_cast<const float4*>(xp)[i * 256 + t];
        s  += v[i].x + v[i].y + v[i].z + v[i].w;
        ss += v[i].x * v[i].x + v[i].y * v[i].y + v[i].z * v[i].z + v[i].w * v[i].w;
    }
#pragma unroll
    for (int m = 16; m > 0; m >>= 1) {
        s  += __shfl_xor_sync(0xffffffffu, s,  m);
        ss += __shfl_xor_sync(0xffffffffu, ss, m);
    }
    __shared__ float rs[8], rss[8];
    if ((t & 31) == 0) { rs[t >> 5] = s; rss[t >> 5] = ss; }
    __syncthreads();
    float tot = 0.f, tots = 0.f;
#pragma unroll
    for (int i = 0; i < 8; i++) { tot += rs[i]; tots += rss[i]; }

    const float invN = 1.0f / (float)(CPG * HWDIM);
    const float mean = tot * invN;
    const float var  = tots * invN - mean * mean;
    const float rstd = rsqrtf(var + EPSV);

#pragma unroll
    for (int i = 0; i < 16; i++) {
        const float ga = gamma[g * CPG + i] * rstd;
        const float be = beta[g * CPG + i];
        float4 o;
        o.x = (v[i].x - mean) * ga + be;
        o.y = (v[i].y - mean) * ga + be;
        o.z = (v[i].z - mean) * ga + be;
        o.w = (v[i].w - mean) * ga + be;
        reinterpret_cast<float4*>(hp)[i * 256 + t] = o;
    }
}

// ============================================================
// 2/4) SGEMM (f32x2): out[b,m,n] = sum_c A[m,c]*Bmat[b,c,n] (+bias,+resid)
//   Block: 64m x 128n, 256 threads, per-thread 4m x 8n (4 n-pairs).
//   A duplicated in smem: As2[k][2m] holds (a,a); B pairs natural.
// ============================================================
#define GS_A 132   // As2 row stride in floats (bank-conflict pad, 16B-aligned)

template <int MODE>
__global__ __launch_bounds__(256)
void gemm_kernel(const float* __restrict__ A,
                 const float* __restrict__ bias,
                 const float* __restrict__ resid,
                 float* __restrict__ outp)
{
    constexpr int M = (MODE == 0) ? C3 : CDIM;
    constexpr int K = CDIM;
    const int b  = blockIdx.z;
    const int m0 = blockIdx.y * 64;
    const int n0 = blockIdx.x * 128;

    const float* Bb = ((MODE == 0) ? g_h : g_ao) + (size_t)b * K * HWDIM;
    float* out = (MODE == 0) ? (float*)g_qkv : outp;

    __shared__ float As2[16][GS_A];   // [k][2m] duplicated
    __shared__ float Bs[16][128];     // [k][n]

    const int t  = threadIdx.x;
    const int ty = t >> 4, tx = t & 15;

    u64 acc[4][4] = {};   // [m][npair] ; 0 bits == (+0.f, +0.f)

    for (int k0 = 0; k0 < K; k0 += 16) {
        {   // A tile 64m x 16k, store duplicated
            const int row = t >> 2, seg = t & 3;
            float4 a = *reinterpret_cast<const float4*>(A + (size_t)(m0 + row) * K + k0 + seg * 4);
            *(u64*)&As2[seg * 4 + 0][2 * row] = pk2(a.x, a.x);
            *(u64*)&As2[seg * 4 + 1][2 * row] = pk2(a.y, a.y);
            *(u64*)&As2[seg * 4 + 2][2 * row] = pk2(a.z, a.z);
            *(u64*)&As2[seg * 4 + 3][2 * row] = pk2(a.w, a.w);
        }
        {   // B tile 16k x 128n
            const int row = t >> 4, c = (t & 15) * 4;
            *reinterpret_cast<float4*>(&Bs[row][c]) =
                *reinterpret_cast<const float4*>(Bb + (size_t)(k0 + row) * HWDIM + n0 + c);
            *reinterpret_cast<float4*>(&Bs[row][c + 64]) =
                *reinterpret_cast<const float4*>(Bb + (size_t)(k0 + row) * HWDIM + n0 + c + 64);
        }
        __syncthreads();
#pragma unroll
        for (int kk = 0; kk < 16; kk++) {
            const u64* ap = (const u64*)&As2[kk][8 * ty];   // (a,a) for m = 4ty..4ty+3
            const u64* bp = (const u64*)&Bs[kk][8 * tx];    // n pairs
            const u64 a0 = ap[0], a1 = ap[1], a2 = ap[2], a3 = ap[3];
            const u64 b0 = bp[0], b1 = bp[1], b2 = bp[2], b3 = bp[3];
            ffma2(acc[0][0], a0, b0); ffma2(acc[0][1], a0, b1); ffma2(acc[0][2], a0, b2); ffma2(acc[0][3], a0, b3);
            ffma2(acc[1][0], a1, b0); ffma2(acc[1][1], a1, b1); ffma2(acc[1][2], a1, b2); ffma2(acc[1][3], a1, b3);
            ffma2(acc[2][0], a2, b0); ffma2(acc[2][1], a2, b1); ffma2(acc[2][2], a2, b2); ffma2(acc[2][3], a2, b3);
            ffma2(acc[3][0], a3, b0); ffma2(acc[3][1], a3, b1); ffma2(acc[3][2], a3, b2); ffma2(acc[3][3], a3, b3);
        }
        __syncthreads();
    }

#pragma unroll
    for (int i = 0; i < 4; i++) {
        const int m = m0 + ty * 4 + i;
        const float bi = bias[m];
        const float2 p0 = upk2(acc[i][0]), p1 = upk2(acc[i][1]);
        const float2 p2 = upk2(acc[i][2]), p3 = upk2(acc[i][3]);
        float4 o1, o2;
        o1.x = p0.x + bi; o1.y = p0.y + bi; o1.z = p1.x + bi; o1.w = p1.y + bi;
        o2.x = p2.x + bi; o2.y = p2.y + bi; o2.z = p3.x + bi; o2.w = p3.y + bi;
        const size_t off = ((size_t)b * M + m) * HWDIM + n0 + 8 * tx;
        if (MODE == 1) {
            const float4 r1 = *reinterpret_cast<const float4*>(resid + off);
            const float4 r2 = *reinterpret_cast<const float4*>(resid + off + 4);
            o1.x += r1.x; o1.y += r1.y; o1.z += r1.z; o1.w += r1.w;
            o2.x += r2.x; o2.y += r2.y; o2.z += r2.z; o2.w += r2.w;
        }
        *reinterpret_cast<float4*>(out + off)     = o1;
        *reinterpret_cast<float4*>(out + off + 4) = o2;
    }
}

// ============================================================
// 3) Flash attention, f32x2. grid = (16 q-tiles, 128 bh). 256 threads.
//    Scores packed along q (Q natural pairs, K duplicated);
//    PV packed along q (P^T natural pairs, V transposed+duplicated).
// ============================================================
#define KS_S 132   // Ks2/Vs2 row stride (floats)
#define ATTN_SMEM ((64*64 + 64*KS_S + 64*KS_S + 64*68) * 4)   // 101376 B

__global__ __launch_bounds__(256)
void attn_kernel()
{
    extern __shared__ float smem[];
    float (*Qs)[64]    = (float(*)[64])(smem);                                   // [c][q]
    float (*Ks2)[KS_S] = (float(*)[KS_S])(smem + 64 * 64);                       // [c][2k] dup
    float (*Vs2)[KS_S] = (float(*)[KS_S])(smem + 64 * 64 + 64 * KS_S);           // [k][2d] dup
    float (*Ps)[68]    = (float(*)[68])(smem + 64 * 64 + 2 * 64 * KS_S);         // [k][q] / [d][q]

    const int qt = blockIdx.x;
    const int bh = blockIdx.y;
    const int b = bh >> 3, head = bh & 7;
    const int n0 = qt * 64;

    const float* qkv = g_qkv + (size_t)b * C3 * HWDIM;
    const float* Qg = qkv + (size_t)(head * 192)       * HWDIM;
    const float* Kg = qkv + (size_t)(head * 192 + 64)  * HWDIM;
    const float* Vg = qkv + (size_t)(head * 192 + 128) * HWDIM;

    const int t  = threadIdx.x;
    const int ty = t >> 4, tx = t & 15;
    const int r = t >> 2, seg = t & 3;

    // Load Q tile (resident): Qs[c][q]
#pragma unroll
    for (int j = 0; j < 4; j++) {
        float4 qv = *reinterpret_cast<const float4*>(Qg + (size_t)r * HWDIM + n0 + seg * 16 + j * 4);
        *reinterpret_cast<float4*>(&Qs[r][seg * 16 + j * 4]) = qv;
    }

    u64 o2[2][4] = {};                       // [qpair][d]: (O[q_even], O[q_odd])
    float m_run[4] = {-1e30f, -1e30f, -1e30f, -1e30f};   // index 2i+h
    float l_run[4] = {};

    for (int kt = 0; kt < 16; kt++) {
        const int k0 = kt * 64;
        // Fill K (pre-scaled, duplicated along k) and V (transposed, duplicated along d)
#pragma unroll
        for (int j = 0; j < 4; j++) {
            const int kc = seg * 16 + j * 4;
            float4 kv = *reinterpret_cast<const float4*>(Kg + (size_t)r * HWDIM + k0 + kc);
            kv.x *= ATTN_SCALE; kv.y *= ATTN_SCALE; kv.z *= ATTN_SCALE; kv.w *= ATTN_SCALE;
            *(u64*)&Ks2[r][2 * (kc + 0)] = pk2(kv.x, kv.x);
            *(u64*)&Ks2[r][2 * (kc + 1)] = pk2(kv.y, kv.y);
            *(u64*)&Ks2[r][2 * (kc + 2)] = pk2(kv.z, kv.z);
            *(u64*)&Ks2[r][2 * (kc + 3)] = pk2(kv.w, kv.w);
            float4 vv = *reinterpret_cast<const float4*>(Vg + (size_t)r * HWDIM + k0 + kc);
            *(u64*)&Vs2[kc + 0][2 * r] = pk2(vv.x, vv.x);
            *(u64*)&Vs2[kc + 1][2 * r] = pk2(vv.y, vv.y);
            *(u64*)&Vs2[kc + 2][2 * r] = pk2(vv.z, vv.z);
            *(u64*)&Vs2[kc + 3][2 * r] = pk2(vv.w, vv.w);
        }
        __syncthreads();

        // S[qpair][k] = sum_c Qpair[c] * Kdup[c][k]
        u64 s2[2][4] = {};
#pragma unroll
        for (int c = 0; c < 64; c++) {
            const u64* qp = (const u64*)&Qs[c][4 * ty];
            const u64* kp = (const u64*)&Ks2[c][8 * tx];
            const u64 q0 = qp[0], q1 = qp[1];
            const u64 ka = kp[0], kb = kp[1], kc_ = kp[2], kd = kp[3];
            ffma2(s2[0][0], q0, ka); ffma2(s2[0][1], q0, kb); ffma2(s2[0][2], q0, kc_); ffma2(s2[0][3], q0, kd);
            ffma2(s2[1][0], q1, ka); ffma2(s2[1][1], q1, kb); ffma2(s2[1][2], q1, kc_); ffma2(s2[1][3], q1, kd);
        }

        // online softmax on q-pairs
#pragma unroll
        for (int i = 0; i < 2; i++) {
            const float2 sv0 = upk2(s2[i][0]), sv1 = upk2(s2[i][1]);
            const float2 sv2 = upk2(s2[i][2]), sv3 = upk2(s2[i][3]);
            float rme = fmaxf(fmaxf(sv0.x, sv1.x), fmaxf(sv2.x, sv3.x));
            float rmo = fmaxf(fmaxf(sv0.y, sv1.y), fmaxf(sv2.y, sv3.y));
#pragma unroll
            for (int d = 8; d > 0; d >>= 1) {
                rme = fmaxf(rme, __shfl_xor_sync(0xffffffffu, rme, d));
                rmo = fmaxf(rmo, __shfl_xor_sync(0xffffffffu, rmo, d));
            }
            const float nme = fmaxf(m_run[2 * i + 0], rme);
            const float nmo = fmaxf(m_run[2 * i + 1], rmo);
            const float alE = __expf(m_run[2 * i + 0] - nme);
            const float alO = __expf(m_run[2 * i + 1] - nmo);
            m_run[2 * i + 0] = nme; m_run[2 * i + 1] = nmo;

            const float e0e = __expf(sv0.x - nme), e1e = __expf(sv1.x - nme);
            const float e2e = __expf(sv2.x - nme), e3e = __expf(sv3.x - nme);
            const float e0o = __expf(sv0.y - nmo), e1o = __expf(sv1.y - nmo);
            const float e2o = __expf(sv2.y - nmo), e3o = __expf(sv3.y - nmo);

            float rle = e0e + e1e + e2e + e3e;
            float rlo = e0o + e1o + e2o + e3o;
#pragma unroll
            for (int d = 8; d > 0; d >>= 1) {
                rle += __shfl_xor_sync(0xffffffffu, rle, d);
                rlo += __shfl_xor_sync(0xffffffffu, rlo, d);
            }
            l_run[2 * i + 0] = l_run[2 * i + 0] * alE + rle;
            l_run[2 * i + 1] = l_run[2 * i + 1] * alO + rlo;

            const u64 ap = pk2(alE, alO);
#pragma unroll
            for (int jd = 0; jd < 4; jd++) o2[i][jd] = fmul2(o2[i][jd], ap);

            // store P transposed: Ps[k][q], q-pair contiguous
            *reinterpret_cast<float2*>(&Ps[4 * tx + 0][4 * ty + 2 * i]) = make_float2(e0e, e0o);
            *reinterpret_cast<float2*>(&Ps[4 * tx + 1][4 * ty + 2 * i]) = make_float2(e1e, e1o);
            *reinterpret_cast<float2*>(&Ps[4 * tx + 2][4 * ty + 2 * i]) = make_float2(e2e, e2o);
            *reinterpret_cast<float2*>(&Ps[4 * tx + 3][4 * ty + 2 * i]) = make_float2(e3e, e3o);
        }
        __syncthreads();

        // O[qpair][d] += Ppair[k] * Vdup[k][d]
#pragma unroll
        for (int k = 0; k < 64; k++) {
            const u64* pp = (const u64*)&Ps[k][4 * ty];
            const u64* vp = (const u64*)&Vs2[k][8 * tx];
            const u64 p0 = pp[0], p1 = pp[1];
            const u64 va = vp[0], vb = vp[1], vc = vp[2], vd = vp[3];
            ffma2(o2[0][0], p0, va); ffma2(o2[0][1], p0, vb); ffma2(o2[0][2], p0, vc); ffma2(o2[0][3], p0, vd);
            ffma2(o2[1][0], p1, va); ffma2(o2[1][1], p1, vb); ffma2(o2[1][2], p1, vc); ffma2(o2[1][3], p1, vd);
        }
        __syncthreads();
    }

    // finalize: stage [d][q] in Ps for coalesced writes
#pragma unroll
    for (int i = 0; i < 2; i++) {
        const float invE = 1.0f / l_run[2 * i + 0];
        const float invO = 1.0f / l_run[2 * i + 1];
#pragma unroll
        for (int jd = 0; jd < 4; jd++) {
            const float2 ov = upk2(o2[i][jd]);
            Ps[4 * tx + jd][4 * ty + 2 * i + 0] = ov.x * invE;
            Ps[4 * tx + jd][4 * ty + 2 * i + 1] = ov.y * invO;
        }
    }
    __syncthreads();

    // Reference scramble: b2 = bh % 16, head2 = bh / 16
    const int b2 = bh & 15, head2 = bh >> 4;
    float* aop = g_ao + ((size_t)b2 * CDIM + head2 * DH) * HWDIM + n0;
#pragma unroll
    for (int j = 0; j < 4; j++) {
        *reinterpret_cast<float4*>(aop + (size_t)r * HWDIM + seg * 16 + j * 4) =
            *reinterpret_cast<const float4*>(&Ps[r][seg * 16 + j * 4]);
    }
}

// ============================================================
// launcher
// ============================================================
extern "C" void kernel_launch(void* const* d_in, const int* in_sizes, int n_in,
                              void* d_out, int out_size)
{
    const float* x      = (const float*)d_in[0];
    const float* gamma  = (const float*)d_in[1];
    const float* beta   = (const float*)d_in[2];
    const float* w_qkv  = (const float*)d_in[3];
    const float* b_qkv  = (const float*)d_in[4];
    const float* w_proj = (const float*)d_in[5];
    const float* b_proj = (const float*)d_in[6];
    float* out = (float*)d_out;

    cudaFuncSetAttribute(attn_kernel, cudaFuncAttributeMaxDynamicSharedMemorySize, ATTN_SMEM);

    // 1) GroupNorm
    groupnorm_kernel<<<BATCH * NGROUPS, 256>>>(x, gamma, beta);

    // 2) QKV GEMM: (1536 x 1024 x 512) per batch
    {
        dim3 grid(HWDIM / 128, C3 / 64, BATCH);
        gemm_kernel<0><<<grid, 256>>>(w_qkv, b_qkv, nullptr, nullptr);
    }

    // 3) Attention
    {
        dim3 grid(HWDIM / 64, BATCH * NH);
        attn_kernel<<<grid, 256, ATTN_SMEM>>>();
    }

    // 4) Proj GEMM + bias + residual
    {
        dim3 grid(HWDIM / 128, CDIM / 64, BATCH);
        gemm_kernel<1><<<grid, 256>>>(w_proj, b_proj, x, out);
    }
}

// round 9
// speedup vs baseline: 2.8576x; 2.8576x over previous
#include <cuda_runtime.h>
#include <cstdint>
#include <math.h>

// ---------------- problem constants ----------------
#define BATCH   16
#define CDIM    512
#define HWDIM   1024            // H*W = 32*32
#define NGROUPS 32
#define CPG     (CDIM / NGROUPS)   // 16
#define NH      8
#define DH      64
#define C3      (3 * CDIM)          // 1536
#define EPSV    1e-5f
#define ATTN_SCALE 0.044194173824159216f   // C ** -0.5 (full dim, per reference)

// ---------------- scratch (device globals: alloc-free rule) ----------------
__device__ float g_hT [BATCH * HWDIM * CDIM];   // groupnorm out, transposed (B, HW, C)
__device__ float g_qkv[BATCH * C3   * HWDIM];   // qkv projection          (B, 3C, HW)
__device__ float g_aoT[BATCH * HWDIM * CDIM];   // attn out, transposed    (B, HW, C) [head-scrambled]

__device__ __forceinline__ float to_tf32(float x) {
    float r; asm("cvt.rna.tf32.f32 %0, %1;" : "=f"(r) : "f"(x)); return r;
}

// mma.sync m16n8k8 tf32 (family-generic, sm_80+): D = A(row) * B(col) + D
__device__ __forceinline__ void mma_tf32(float& c0, float& c1, float& c2, float& c3,
                                         uint32_t a0, uint32_t a1, uint32_t a2, uint32_t a3,
                                         uint32_t b0, uint32_t b1) {
    asm volatile(
        "mma.sync.aligned.m16n8k8.row.col.f32.tf32.tf32.f32 "
        "{%0,%1,%2,%3}, {%4,%5,%6,%7}, {%8,%9}, {%0,%1,%2,%3};\n"
        : "+f"(c0), "+f"(c1), "+f"(c2), "+f"(c3)
        : "r"(a0), "r"(a1), "r"(a2), "r"(a3), "r"(b0), "r"(b1));
}

// ============================================================
// 1) GroupNorm -> writes transposed g_hT[b][hw][c]
// ============================================================
__global__ __launch_bounds__(256)
void groupnorm_kernel(const float* __restrict__ x,
                      const float* __restrict__ gamma,
                      const float* __restrict__ beta)
{
    const int bg = blockIdx.x;
    const int b = bg / NGROUPS, g = bg % NGROUPS;
    const int t = threadIdx.x;
    const float* xp = x + (size_t)(b * CDIM + g * CPG) * HWDIM;

    // float4 i*256+t = channel i, hw 4t..4t+3
    float4 v[16];
    float s = 0.f, ss = 0.f;
#pragma unroll
    for (int i = 0; i < 16; i++) {
        v[i] = reinterpret_cast<const float4*>(xp)[i * 256 + t];
        s  += v[i].x + v[i].y + v[i].z + v[i].w;
        ss += v[i].x * v[i].x + v[i].y * v[i].y + v[i].z * v[i].z + v[i].w * v[i].w;
    }
#pragma unroll
    for (int m = 16; m > 0; m >>= 1) {
        s  += __shfl_xor_sync(0xffffffffu, s,  m);
        ss += __shfl_xor_sync(0xffffffffu, ss, m);
    }
    __shared__ float rs[8], rss[8];
    if ((t & 31) == 0) { rs[t >> 5] = s; rss[t >> 5] = ss; }
    __syncthreads();
    float tot = 0.f, tots = 0.f;
#pragma unroll
    for (int i = 0; i < 8; i++) { tot += rs[i]; tots += rss[i]; }

    const float invN = 1.0f / (float)(CPG * HWDIM);
    const float mean = tot * invN;
    const float var  = tots * invN - mean * mean;
    const float rstd = rsqrtf(var + EPSV);

    float ga[16], be[16];
#pragma unroll
    for (int i = 0; i < 16; i++) {
        ga[i] = gamma[g * CPG + i] * rstd;
        be[i] = beta[g * CPG + i];
    }
#pragma unroll
    for (int i = 0; i < 16; i++) {
        v[i].x = (v[i].x - mean) * ga[i] + be[i];
        v[i].y = (v[i].y - mean) * ga[i] + be[i];
        v[i].z = (v[i].z - mean) * ga[i] + be[i];
        v[i].w = (v[i].w - mean) * ga[i] + be[i];
    }
    // transposed write: g_hT[b][hw][g*16 + i]
    float* hp = g_hT + ((size_t)b * HWDIM + 4 * t) * CDIM + g * CPG;
#pragma unroll
    for (int j = 0; j < 4; j++) {
        const float* c0 = (j == 0) ? &v[0].x : (j == 1) ? &v[0].y : (j == 2) ? &v[0].z : &v[0].w;
        float4 o0, o1, o2, o3;
        o0.x = c0[0*4];  o0.y = c0[1*4];  o0.z = c0[2*4];  o0.w = c0[3*4];
        o1.x = c0[4*4];  o1.y = c0[5*4];  o1.z = c0[6*4];  o1.w = c0[7*4];
        o2.x = c0[8*4];  o2.y = c0[9*4];  o2.z = c0[10*4]; o2.w = c0[11*4];
        o3.x = c0[12*4]; o3.y = c0[13*4]; o3.z = c0[14*4]; o3.w = c0[15*4];
        float* row = hp + (size_t)j * CDIM;
        reinterpret_cast<float4*>(row)[0] = o0;
        reinterpret_cast<float4*>(row)[1] = o1;
        reinterpret_cast<float4*>(row)[2] = o2;
        reinterpret_cast<float4*>(row)[3] = o3;
    }
}

// ============================================================
// 2/4) mma.sync tf32 GEMM: out[b,m,n] = sum_c A[m,c]*Bsrc[b,n,c] (+bias,+resid)
//   A K-major [M,512]; Bsrc [B,HW,512] K-major -> row.col mma, no transposes.
//   CTA: 128m x 128n x 32k chunks. 8 warps (2m x 4n), warp = 64m x 32n.
//   Warp tile: 4 mtiles(16) x 4 ntiles(8); k in 4 steps of 8.
// ============================================================
#define LDA 36   // smem row stride (floats): addr = row*36 + k -> 4*gid+tig mod 32, conflict-free

template <int MODE>
__global__ __launch_bounds__(256, 2)
void gemm_mma(const float* __restrict__ A,
              const float* __restrict__ bias,
              const float* __restrict__ resid,
              float* __restrict__ outp)
{
    constexpr int M = (MODE == 0) ? C3 : CDIM;
    __shared__ float As[128][LDA];   // [m][k]
    __shared__ float Bs[128][LDA];   // [n][k]

    const int b  = blockIdx.z;
    const int m0 = blockIdx.y * 128;
    const int n0 = blockIdx.x * 128;
    const float* Ag = A + (size_t)m0 * CDIM;
    const float* Bg = ((MODE == 0) ? g_hT : g_aoT) + ((size_t)b * HWDIM + n0) * CDIM;
    float* out = (MODE == 0) ? (float*)g_qkv : outp;

    const int t = threadIdx.x;
    const int wid = t >> 5, lane = t & 31;
    const int gid = lane >> 2, tig = lane & 3;
    const int wm = (wid & 1) * 64;    // warp m offset in CTA tile
    const int wn = (wid >> 1) * 32;   // warp n offset

    float acc[4][4][4] = {};          // [mtile][ntile][reg]

    for (int ch = 0; ch < 16; ch++) {
        const int k0 = ch * 32;
        // stage A,B chunk: 128 rows x 32 floats each
#pragma unroll
        for (int it = 0; it < 4; it++) {
            const int idx = it * 256 + t;
            const int row = idx >> 3, c4 = idx & 7;
            float4 a = *reinterpret_cast<const float4*>(Ag + (size_t)row * CDIM + k0 + c4 * 4);
            a.x = to_tf32(a.x); a.y = to_tf32(a.y); a.z = to_tf32(a.z); a.w = to_tf32(a.w);
            *reinterpret_cast<float4*>(&As[row][c4 * 4]) = a;
            float4 bv = *reinterpret_cast<const float4*>(Bg + (size_t)row * CDIM + k0 + c4 * 4);
            bv.x = to_tf32(bv.x); bv.y = to_tf32(bv.y); bv.z = to_tf32(bv.z); bv.w = to_tf32(bv.w);
            *reinterpret_cast<float4*>(&Bs[row][c4 * 4]) = bv;
        }
        __syncthreads();

#pragma unroll
        for (int ks = 0; ks < 4; ks++) {
            const int k = ks * 8;
            uint32_t afr[4][4];
#pragma unroll
            for (int mt = 0; mt < 4; mt++) {
                const int mr = wm + mt * 16;
                afr[mt][0] = __float_as_uint(As[mr + gid    ][k + tig    ]);
                afr[mt][1] = __float_as_uint(As[mr + gid + 8][k + tig    ]);
                afr[mt][2] = __float_as_uint(As[mr + gid    ][k + tig + 4]);
                afr[mt][3] = __float_as_uint(As[mr + gid + 8][k + tig + 4]);
            }
            uint32_t bfr[4][2];
#pragma unroll
            for (int nt = 0; nt < 4; nt++) {
                const int nr = wn + nt * 8;
                bfr[nt][0] = __float_as_uint(Bs[nr + gid][k + tig    ]);
                bfr[nt][1] = __float_as_uint(Bs[nr + gid][k + tig + 4]);
            }
#pragma unroll
            for (int mt = 0; mt < 4; mt++)
#pragma unroll
                for (int nt = 0; nt < 4; nt++)
                    mma_tf32(acc[mt][nt][0], acc[mt][nt][1], acc[mt][nt][2], acc[mt][nt][3],
                             afr[mt][0], afr[mt][1], afr[mt][2], afr[mt][3],
                             bfr[nt][0], bfr[nt][1]);
        }
        __syncthreads();
    }

    // epilogue: c0,c1 at (row gid, cols 2tig,2tig+1); c2,c3 at (row gid+8)
#pragma unroll
    for (int mt = 0; mt < 4; mt++) {
        const int r0 = m0 + wm + mt * 16 + gid;
        const int r1 = r0 + 8;
        const float bi0 = bias[r0], bi1 = bias[r1];
#pragma unroll
        for (int nt = 0; nt < 4; nt++) {
            const int n = n0 + wn + nt * 8 + 2 * tig;
            float2 o0, o1;
            o0.x = acc[mt][nt][0] + bi0; o0.y = acc[mt][nt][1] + bi0;
            o1.x = acc[mt][nt][2] + bi1; o1.y = acc[mt][nt][3] + bi1;
            const size_t off0 = ((size_t)b * M + r0) * HWDIM + n;
            const size_t off1 = ((size_t)b * M + r1) * HWDIM + n;
            if (MODE == 1) {
                const float2 x0 = *reinterpret_cast<const float2*>(resid + off0);
                const float2 x1 = *reinterpret_cast<const float2*>(resid + off1);
                o0.x += x0.x; o0.y += x0.y;
                o1.x += x1.x; o1.y += x1.y;
            }
            *reinterpret_cast<float2*>(out + off0) = o0;
            *reinterpret_cast<float2*>(out + off1) = o1;
        }
    }
}

// ============================================================
// 3) Flash attention, fp32 FFMA (round-4 proven version).
//    Writes transposed+scrambled g_aoT[b2][hw][head2*64 + d].
// ============================================================
#define ATTN_SMEM ((64 * 64 * 2 + 64 * 68 * 2) * 4)   // 67584 B

__global__ __launch_bounds__(256)
void attn_kernel()
{
    extern __shared__ float sm[];
    float (*Qs)[64] = (float(*)[64])(sm);
    float (*Ks)[64] = (float(*)[64])(sm + 64 * 64);
    float (*Vs)[68] = (float(*)[68])(sm + 2 * 64 * 64);
    float (*Ps)[68] = (float(*)[68])(sm + 2 * 64 * 64 + 64 * 68);

    const int qt = blockIdx.x;
    const int bh = blockIdx.y;
    const int b = bh >> 3, head = bh & 7;
    const int n0 = qt * 64;

    const float* qkv = g_qkv + (size_t)b * C3 * HWDIM;
    const float* Qg = qkv + (size_t)(head * 192)       * HWDIM;
    const float* Kg = qkv + (size_t)(head * 192 + 64)  * HWDIM;
    const float* Vg = qkv + (size_t)(head * 192 + 128) * HWDIM;

    const int t  = threadIdx.x;
    const int ty = t >> 4, tx = t & 15;
    const int r = t >> 2, seg = t & 3;

#pragma unroll
    for (int j = 0; j < 4; j++) {
        float4 qv = *reinterpret_cast<const float4*>(Qg + (size_t)r * HWDIM + n0 + seg * 16 + j * 4);
        *reinterpret_cast<float4*>(&Qs[r][seg * 16 + j * 4]) = qv;
    }

    float o[4][4] = {};
    float m_run[4] = {-1e30f, -1e30f, -1e30f, -1e30f};
    float l_run[4] = {};

    for (int kt = 0; kt < 16; kt++) {
        const int k0 = kt * 64;
#pragma unroll
        for (int j = 0; j < 4; j++) {
            float4 kv = *reinterpret_cast<const float4*>(Kg + (size_t)r * HWDIM + k0 + seg * 16 + j * 4);
            kv.x *= ATTN_SCALE; kv.y *= ATTN_SCALE; kv.z *= ATTN_SCALE; kv.w *= ATTN_SCALE;
            *reinterpret_cast<float4*>(&Ks[r][seg * 16 + j * 4]) = kv;
            float4 vv = *reinterpret_cast<const float4*>(Vg + (size_t)r * HWDIM + k0 + seg * 16 + j * 4);
            Vs[seg * 16 + j * 4 + 0][r] = vv.x;
            Vs[seg * 16 + j * 4 + 1][r] = vv.y;
            Vs[seg * 16 + j * 4 + 2][r] = vv.z;
            Vs[seg * 16 + j * 4 + 3][r] = vv.w;
        }
        __syncthreads();

        float s_[4][4] = {};
#pragma unroll
        for (int c = 0; c < 64; c++) {
            const float4 ra = *reinterpret_cast<const float4*>(&Qs[c][ty * 4]);
            const float4 rb = *reinterpret_cast<const float4*>(&Ks[c][tx * 4]);
            const float a0 = ra.x, a1 = ra.y, a2 = ra.z, a3 = ra.w;
            const float b0 = rb.x, b1 = rb.y, b2 = rb.z, b3 = rb.w;
            s_[0][0] += a0 * b0; s_[0][1] += a0 * b1; s_[0][2] += a0 * b2; s_[0][3] += a0 * b3;
            s_[1][0] += a1 * b0; s_[1][1] += a1 * b1; s_[1][2] += a1 * b2; s_[1][3] += a1 * b3;
            s_[2][0] += a2 * b0; s_[2][1] += a2 * b1; s_[2][2] += a2 * b2; s_[2][3] += a2 * b3;
            s_[3][0] += a3 * b0; s_[3][1] += a3 * b1; s_[3][2] += a3 * b2; s_[3][3] += a3 * b3;
        }

#pragma unroll
        for (int i = 0; i < 4; i++) {
            float rm = fmaxf(fmaxf(s_[i][0], s_[i][1]), fmaxf(s_[i][2], s_[i][3]));
#pragma unroll
            for (int d = 8; d > 0; d >>= 1)
                rm = fmaxf(rm, __shfl_xor_sync(0xffffffffu, rm, d));
            const float newm  = fmaxf(m_run[i], rm);
            const float alpha = __expf(m_run[i] - newm);
            m_run[i] = newm;
            float rl = 0.f;
#pragma unroll
            for (int j = 0; j < 4; j++) {
                s_[i][j] = __expf(s_[i][j] - newm);
                rl += s_[i][j];
            }
#pragma unroll
            for (int d = 8; d > 0; d >>= 1)
                rl += __shfl_xor_sync(0xffffffffu, rl, d);
            l_run[i] = l_run[i] * alpha + rl;
#pragma unroll
            for (int j = 0; j < 4; j++) o[i][j] *= alpha;
            float4 pv; pv.x = s_[i][0]; pv.y = s_[i][1]; pv.z = s_[i][2]; pv.w = s_[i][3];
            *reinterpret_cast<float4*>(&Ps[ty * 4 + i][tx * 4]) = pv;
        }
        __syncthreads();

#pragma unroll
        for (int k = 0; k < 64; k++) {
            const float4 rv = *reinterpret_cast<const float4*>(&Vs[k][tx * 4]);
            const float p0 = Ps[ty * 4 + 0][k];
            const float p1 = Ps[ty * 4 + 1][k];
            const float p2 = Ps[ty * 4 + 2][k];
            const float p3 = Ps[ty * 4 + 3][k];
            o[0][0] += p0 * rv.x; o[0][1] += p0 * rv.y; o[0][2] += p0 * rv.z; o[0][3] += p0 * rv.w;
            o[1][0] += p1 * rv.x; o[1][1] += p1 * rv.y; o[1][2] += p1 * rv.z; o[1][3] += p1 * rv.w;
            o[2][0] += p2 * rv.x; o[2][1] += p2 * rv.y; o[2][2] += p2 * rv.z; o[2][3] += p2 * rv.w;
            o[3][0] += p3 * rv.x; o[3][1] += p3 * rv.y; o[3][2] += p3 * rv.z; o[3][3] += p3 * rv.w;
        }
        __syncthreads();
    }

    // Direct transposed write: reference scramble b2 = bh%16, head2 = bh/16.
    const int b2 = bh & 15, head2 = bh >> 4;
    float* aop = g_aoT + ((size_t)b2 * HWDIM + n0) * CDIM + head2 * DH + tx * 4;
#pragma unroll
    for (int i = 0; i < 4; i++) {
        const float inv_l = 1.0f / l_run[i];
        float4 w;
        w.x = o[i][0] * inv_l; w.y = o[i][1] * inv_l;
        w.z = o[i][2] * inv_l; w.w = o[i][3] * inv_l;
        *reinterpret_cast<float4*>(aop + (size_t)(ty * 4 + i) * CDIM) = w;
    }
}

// ============================================================
// launcher
// ============================================================
extern "C" void kernel_launch(void* const* d_in, const int* in_sizes, int n_in,
                              void* d_out, int out_size)
{
    const float* x      = (const float*)d_in[0];
    const float* gamma  = (const float*)d_in[1];
    const float* beta   = (const float*)d_in[2];
    const float* w_qkv  = (const float*)d_in[3];
    const float* b_qkv  = (const float*)d_in[4];
    const float* w_proj = (const float*)d_in[5];
    const float* b_proj = (const float*)d_in[6];
    float* out = (float*)d_out;

    cudaFuncSetAttribute(attn_kernel, cudaFuncAttributeMaxDynamicSharedMemorySize, ATTN_SMEM);

    // 1) GroupNorm (writes hT)
    groupnorm_kernel<<<BATCH * NGROUPS, 256>>>(x, gamma, beta);

    // 2) QKV GEMM (mma.sync tf32): per batch 1536 x 1024 x 512
    {
        dim3 grid(HWDIM / 128, C3 / 128, BATCH);
        gemm_mma<0><<<grid, 256>>>(w_qkv, b_qkv, nullptr, nullptr);
    }

    // 3) Attention (fp32 flash, writes aoT scrambled)
    {
        dim3 grid(HWDIM / 64, BATCH * NH);
        attn_kernel<<<grid, 256, ATTN_SMEM>>>();
    }

    // 4) Proj GEMM (mma.sync tf32) + bias + residual
    {
        dim3 grid(HWDIM / 128, CDIM / 128, BATCH);
        gemm_mma<1><<<grid, 256>>>(w_proj, b_proj, x, out);
    }
}

// round 11
// speedup vs baseline: 5.8940x; 2.0625x over previous
#include <cuda_runtime.h>
#include <cstdint>
#include <math.h>

// ---------------- problem constants ----------------
#define BATCH   16
#define CDIM    512
#define HWDIM   1024            // H*W = 32*32
#define NGROUPS 32
#define CPG     (CDIM / NGROUPS)   // 16
#define NH      8
#define DH      64
#define C3      (3 * CDIM)          // 1536
#define EPSV    1e-5f
#define ATTN_SCALE 0.044194173824159216f   // C ** -0.5 (full dim, per reference)

// ---------------- scratch (device globals: alloc-free rule) ----------------
__device__ float g_hT [BATCH * HWDIM * CDIM];   // groupnorm out, transposed (B, HW, C)
__device__ float g_qkv[BATCH * C3   * HWDIM];   // qkv projection          (B, 3C, HW)
__device__ float g_aoT[BATCH * HWDIM * CDIM];   // attn out, transposed    (B, HW, C) [head-scrambled]

__device__ __forceinline__ float to_tf32(float x) {
    float r; asm("cvt.rna.tf32.f32 %0, %1;" : "=f"(r) : "f"(x)); return r;
}

// mma.sync m16n8k8 tf32 (family-generic, sm_80+): D = A(row) * B(col) + D
__device__ __forceinline__ void mma_tf32(float& c0, float& c1, float& c2, float& c3,
                                         uint32_t a0, uint32_t a1, uint32_t a2, uint32_t a3,
                                         uint32_t b0, uint32_t b1) {
    asm volatile(
        "mma.sync.aligned.m16n8k8.row.col.f32.tf32.tf32.f32 "
        "{%0,%1,%2,%3}, {%4,%5,%6,%7}, {%8,%9}, {%0,%1,%2,%3};\n"
        : "+f"(c0), "+f"(c1), "+f"(c2), "+f"(c3)
        : "r"(a0), "r"(a1), "r"(a2), "r"(a3), "r"(b0), "r"(b1));
}

// ============================================================
// 1) GroupNorm -> writes transposed g_hT[b][hw][c]
// ============================================================
__global__ __launch_bounds__(256)
void groupnorm_kernel(const float* __restrict__ x,
                      const float* __restrict__ gamma,
                      const float* __restrict__ beta)
{
    const int bg = blockIdx.x;
    const int b = bg / NGROUPS, g = bg % NGROUPS;
    const int t = threadIdx.x;
    const float* xp = x + (size_t)(b * CDIM + g * CPG) * HWDIM;

    float4 v[16];
    float s = 0.f, ss = 0.f;
#pragma unroll
    for (int i = 0; i < 16; i++) {
        v[i] = reinterpret_cast<const float4*>(xp)[i * 256 + t];
        s  += v[i].x + v[i].y + v[i].z + v[i].w;
        ss += v[i].x * v[i].x + v[i].y * v[i].y + v[i].z * v[i].z + v[i].w * v[i].w;
    }
#pragma unroll
    for (int m = 16; m > 0; m >>= 1) {
        s  += __shfl_xor_sync(0xffffffffu, s,  m);
        ss += __shfl_xor_sync(0xffffffffu, ss, m);
    }
    __shared__ float rs[8], rss[8];
    if ((t & 31) == 0) { rs[t >> 5] = s; rss[t >> 5] = ss; }
    __syncthreads();
    float tot = 0.f, tots = 0.f;
#pragma unroll
    for (int i = 0; i < 8; i++) { tot += rs[i]; tots += rss[i]; }

    const float invN = 1.0f / (float)(CPG * HWDIM);
    const float mean = tot * invN;
    const float var  = tots * invN - mean * mean;
    const float rstd = rsqrtf(var + EPSV);

    float ga[16], be[16];
#pragma unroll
    for (int i = 0; i < 16; i++) {
        ga[i] = gamma[g * CPG + i] * rstd;
        be[i] = beta[g * CPG + i];
    }
#pragma unroll
    for (int i = 0; i < 16; i++) {
        v[i].x = (v[i].x - mean) * ga[i] + be[i];
        v[i].y = (v[i].y - mean) * ga[i] + be[i];
        v[i].z = (v[i].z - mean) * ga[i] + be[i];
        v[i].w = (v[i].w - mean) * ga[i] + be[i];
    }
    float* hp = g_hT + ((size_t)b * HWDIM + 4 * t) * CDIM + g * CPG;
#pragma unroll
    for (int j = 0; j < 4; j++) {
        const float* c0 = (j == 0) ? &v[0].x : (j == 1) ? &v[0].y : (j == 2) ? &v[0].z : &v[0].w;
        float4 o0, o1, o2, o3;
        o0.x = c0[0*4];  o0.y = c0[1*4];  o0.z = c0[2*4];  o0.w = c0[3*4];
        o1.x = c0[4*4];  o1.y = c0[5*4];  o1.z = c0[6*4];  o1.w = c0[7*4];
        o2.x = c0[8*4];  o2.y = c0[9*4];  o2.z = c0[10*4]; o2.w = c0[11*4];
        o3.x = c0[12*4]; o3.y = c0[13*4]; o3.z = c0[14*4]; o3.w = c0[15*4];
        float* row = hp + (size_t)j * CDIM;
        reinterpret_cast<float4*>(row)[0] = o0;
        reinterpret_cast<float4*>(row)[1] = o1;
        reinterpret_cast<float4*>(row)[2] = o2;
        reinterpret_cast<float4*>(row)[3] = o3;
    }
}

// ============================================================
// 2/4) mma.sync tf32 GEMM (unchanged from round 9, proven)
// ============================================================
#define LDA 36

template <int MODE>
__global__ __launch_bounds__(256, 2)
void gemm_mma(const float* __restrict__ A,
              const float* __restrict__ bias,
              const float* __restrict__ resid,
              float* __restrict__ outp)
{
    constexpr int M = (MODE == 0) ? C3 : CDIM;
    __shared__ float As[128][LDA];
    __shared__ float Bs[128][LDA];

    const int b  = blockIdx.z;
    const int m0 = blockIdx.y * 128;
    const int n0 = blockIdx.x * 128;
    const float* Ag = A + (size_t)m0 * CDIM;
    const float* Bg = ((MODE == 0) ? g_hT : g_aoT) + ((size_t)b * HWDIM + n0) * CDIM;
    float* out = (MODE == 0) ? (float*)g_qkv : outp;

    const int t = threadIdx.x;
    const int wid = t >> 5, lane = t & 31;
    const int gid = lane >> 2, tig = lane & 3;
    const int wm = (wid & 1) * 64;
    const int wn = (wid >> 1) * 32;

    float acc[4][4][4] = {};

    for (int ch = 0; ch < 16; ch++) {
        const int k0 = ch * 32;
#pragma unroll
        for (int it = 0; it < 4; it++) {
            const int idx = it * 256 + t;
            const int row = idx >> 3, c4 = idx & 7;
            float4 a = *reinterpret_cast<const float4*>(Ag + (size_t)row * CDIM + k0 + c4 * 4);
            a.x = to_tf32(a.x); a.y = to_tf32(a.y); a.z = to_tf32(a.z); a.w = to_tf32(a.w);
            *reinterpret_cast<float4*>(&As[row][c4 * 4]) = a;
            float4 bv = *reinterpret_cast<const float4*>(Bg + (size_t)row * CDIM + k0 + c4 * 4);
            bv.x = to_tf32(bv.x); bv.y = to_tf32(bv.y); bv.z = to_tf32(bv.z); bv.w = to_tf32(bv.w);
            *reinterpret_cast<float4*>(&Bs[row][c4 * 4]) = bv;
        }
        __syncthreads();

#pragma unroll
        for (int ks = 0; ks < 4; ks++) {
            const int k = ks * 8;
            uint32_t afr[4][4];
#pragma unroll
            for (int mt = 0; mt < 4; mt++) {
                const int mr = wm + mt * 16;
                afr[mt][0] = __float_as_uint(As[mr + gid    ][k + tig    ]);
                afr[mt][1] = __float_as_uint(As[mr + gid + 8][k + tig    ]);
                afr[mt][2] = __float_as_uint(As[mr + gid    ][k + tig + 4]);
                afr[mt][3] = __float_as_uint(As[mr + gid + 8][k + tig + 4]);
            }
            uint32_t bfr[4][2];
#pragma unroll
            for (int nt = 0; nt < 4; nt++) {
                const int nr = wn + nt * 8;
                bfr[nt][0] = __float_as_uint(Bs[nr + gid][k + tig    ]);
                bfr[nt][1] = __float_as_uint(Bs[nr + gid][k + tig + 4]);
            }
#pragma unroll
            for (int mt = 0; mt < 4; mt++)
#pragma unroll
                for (int nt = 0; nt < 4; nt++)
                    mma_tf32(acc[mt][nt][0], acc[mt][nt][1], acc[mt][nt][2], acc[mt][nt][3],
                             afr[mt][0], afr[mt][1], afr[mt][2], afr[mt][3],
                             bfr[nt][0], bfr[nt][1]);
        }
        __syncthreads();
    }

#pragma unroll
    for (int mt = 0; mt < 4; mt++) {
        const int r0 = m0 + wm + mt * 16 + gid;
        const int r1 = r0 + 8;
        const float bi0 = bias[r0], bi1 = bias[r1];
#pragma unroll
        for (int nt = 0; nt < 4; nt++) {
            const int n = n0 + wn + nt * 8 + 2 * tig;
            float2 o0, o1;
            o0.x = acc[mt][nt][0] + bi0; o0.y = acc[mt][nt][1] + bi0;
            o1.x = acc[mt][nt][2] + bi1; o1.y = acc[mt][nt][3] + bi1;
            const size_t off0 = ((size_t)b * M + r0) * HWDIM + n;
            const size_t off1 = ((size_t)b * M + r1) * HWDIM + n;
            if (MODE == 1) {
                const float2 x0 = *reinterpret_cast<const float2*>(resid + off0);
                const float2 x1 = *reinterpret_cast<const float2*>(resid + off1);
                o0.x += x0.x; o0.y += x0.y;
                o1.x += x1.x; o1.y += x1.y;
            }
            *reinterpret_cast<float2*>(out + off0) = o0;
            *reinterpret_cast<float2*>(out + off1) = o1;
        }
    }
}

// ============================================================
// 3) Flash attention on tensor cores (mma.sync tf32).
//    128 threads = 4 warps; warp w owns q rows [16w, 16w+16).
//    Smem layouts (all natural, zero transposes):
//      Qs[c][q]  <- Q gmem [c][hw] slice      (A-frag: Qs[k+tig][q0+gid])
//      Ks[c][k]  <- K gmem                    (B-frag: Ks[k+tig][kn0+gid])
//      Vs[d][k]  <- V gmem                    (B-frag: Vs[dn0+gid][k+tig])
//      Ps[q][k]  <- P fragments (per-warp rows, __syncwarp only)
//    Writes transposed+scrambled g_aoT[b2][hw][head2*64 + d].
// ============================================================
#define ASTR 68                       // smem row stride (floats)
#define ATTN_SMEM (4 * 64 * ASTR * 4) // 69632 B

__global__ __launch_bounds__(128)
void attn_kernel()
{
    extern __shared__ float sm[];
    float (*Qs)[ASTR] = (float(*)[ASTR])(sm);
    float (*Ks)[ASTR] = (float(*)[ASTR])(sm + 64 * ASTR);
    float (*Vs)[ASTR] = (float(*)[ASTR])(sm + 2 * 64 * ASTR);
    float (*Ps)[ASTR] = (float(*)[ASTR])(sm + 3 * 64 * ASTR);

    const int qt = blockIdx.x;         // 0..15
    const int bh = blockIdx.y;         // 0..127
    const int b = bh >> 3, head = bh & 7;
    const int n0 = qt * 64;

    const float* qkv = g_qkv + (size_t)b * C3 * HWDIM;
    const float* Qg = qkv + (size_t)(head * 192)       * HWDIM;
    const float* Kg = qkv + (size_t)(head * 192 + 64)  * HWDIM;
    const float* Vg = qkv + (size_t)(head * 192 + 128) * HWDIM;

    const int t = threadIdx.x;
    const int wid = t >> 5, lane = t & 31;
    const int gid = lane >> 2, tig = lane & 3;
    const int q0w = wid * 16;          // warp's q base (local)

    // stage Q once: rows c=0..63, cols q (scaled + tf32)
    {
        const int col4 = (t & 15) * 4;
#pragma unroll
        for (int p = 0; p < 8; p++) {
            const int row = (t >> 4) + p * 8;
            float4 qv = *reinterpret_cast<const float4*>(Qg + (size_t)row * HWDIM + n0 + col4);
            qv.x = to_tf32(qv.x * ATTN_SCALE); qv.y = to_tf32(qv.y * ATTN_SCALE);
            qv.z = to_tf32(qv.z * ATTN_SCALE); qv.w = to_tf32(qv.w * ATTN_SCALE);
            *reinterpret_cast<float4*>(&Qs[row][col4]) = qv;
        }
    }

    float o_acc[8][4] = {};            // [d-tile][c0..c3], rows gid / gid+8
    float m0r = -1e30f, m1r = -1e30f;
    float l0r = 0.f, l1r = 0.f;

    for (int kt = 0; kt < 16; kt++) {
        const int k0 = kt * 64;
        // stage K and V tiles (64 rows x 64 cols each)
        {
            const int col4 = (t & 15) * 4;
#pragma unroll
            for (int p = 0; p < 8; p++) {
                const int row = (t >> 4) + p * 8;
                float4 kv = *reinterpret_cast<const float4*>(Kg + (size_t)row * HWDIM + k0 + col4);
                kv.x = to_tf32(kv.x); kv.y = to_tf32(kv.y);
                kv.z = to_tf32(kv.z); kv.w = to_tf32(kv.w);
                *reinterpret_cast<float4*>(&Ks[row][col4]) = kv;
                float4 vv = *reinterpret_cast<const float4*>(Vg + (size_t)row * HWDIM + k0 + col4);
                vv.x = to_tf32(vv.x); vv.y = to_tf32(vv.y);
                vv.z = to_tf32(vv.z); vv.w = to_tf32(vv.w);
                *reinterpret_cast<float4*>(&Vs[row][col4]) = vv;
            }
        }
        __syncthreads();

        // S = Q K^T : warp computes S[16q][64k] in 8 ntiles
        float s_acc[8][4] = {};
#pragma unroll
        for (int ks = 0; ks < 8; ks++) {
            const int k = ks * 8;      // c-dim step
            uint32_t a0 = __float_as_uint(Qs[k + tig    ][q0w + gid    ]);
            uint32_t a1 = __float_as_uint(Qs[k + tig    ][q0w + gid + 8]);
            uint32_t a2 = __float_as_uint(Qs[k + tig + 4][q0w + gid    ]);
            uint32_t a3 = __float_as_uint(Qs[k + tig + 4][q0w + gid + 8]);
#pragma unroll
            for (int nt = 0; nt < 8; nt++) {
                const int kn0 = nt * 8;
                uint32_t b0 = __float_as_uint(Ks[k + tig    ][kn0 + gid]);
                uint32_t b1 = __float_as_uint(Ks[k + tig + 4][kn0 + gid]);
                mma_tf32(s_acc[nt][0], s_acc[nt][1], s_acc[nt][2], s_acc[nt][3],
                         a0, a1, a2, a3, b0, b1);
            }
        }

        // online softmax on fragments (rows q0w+gid and q0w+gid+8)
        float mx0 = -1e30f, mx1 = -1e30f;
#pragma unroll
        for (int nt = 0; nt < 8; nt++) {
            mx0 = fmaxf(mx0, fmaxf(s_acc[nt][0], s_acc[nt][1]));
            mx1 = fmaxf(mx1, fmaxf(s_acc[nt][2], s_acc[nt][3]));
        }
        mx0 = fmaxf(mx0, __shfl_xor_sync(0xffffffffu, mx0, 1));
        mx0 = fmaxf(mx0, __shfl_xor_sync(0xffffffffu, mx0, 2));
        mx1 = fmaxf(mx1, __shfl_xor_sync(0xffffffffu, mx1, 1));
        mx1 = fmaxf(mx1, __shfl_xor_sync(0xffffffffu, mx1, 2));

        const float nm0 = fmaxf(m0r, mx0);
        const float nm1 = fmaxf(m1r, mx1);
        const float al0 = __expf(m0r - nm0);
        const float al1 = __expf(m1r - nm1);
        m0r = nm0; m1r = nm1;

        float rl0 = 0.f, rl1 = 0.f;
#pragma unroll
        for (int nt = 0; nt < 8; nt++) {
            s_acc[nt][0] = __expf(s_acc[nt][0] - nm0);
            s_acc[nt][1] = __expf(s_acc[nt][1] - nm0);
            s_acc[nt][2] = __expf(s_acc[nt][2] - nm1);
            s_acc[nt][3] = __expf(s_acc[nt][3] - nm1);
            rl0 += s_acc[nt][0] + s_acc[nt][1];
            rl1 += s_acc[nt][2] + s_acc[nt][3];
        }
        rl0 += __shfl_xor_sync(0xffffffffu, rl0, 1);
        rl0 += __shfl_xor_sync(0xffffffffu, rl0, 2);
        rl1 += __shfl_xor_sync(0xffffffffu, rl1, 1);
        rl1 += __shfl_xor_sync(0xffffffffu, rl1, 2);
        l0r = l0r * al0 + rl0;
        l1r = l1r * al1 + rl1;

#pragma unroll
        for (int nt = 0; nt < 8; nt++) {
            o_acc[nt][0] *= al0; o_acc[nt][1] *= al0;
            o_acc[nt][2] *= al1; o_acc[nt][3] *= al1;
        }

        // write P fragments to Ps[q][k] (tf32-rounded), per-warp rows
#pragma unroll
        for (int nt = 0; nt < 8; nt++) {
            float2 p0, p1;
            p0.x = to_tf32(s_acc[nt][0]); p0.y = to_tf32(s_acc[nt][1]);
            p1.x = to_tf32(s_acc[nt][2]); p1.y = to_tf32(s_acc[nt][3]);
            *reinterpret_cast<float2*>(&Ps[q0w + gid    ][nt * 8 + 2 * tig]) = p0;
            *reinterpret_cast<float2*>(&Ps[q0w + gid + 8][nt * 8 + 2 * tig]) = p1;
        }
        __syncwarp();

        // O += P V : k-dim = 64 keys, 8 d-tiles
#pragma unroll
        for (int ks = 0; ks < 8; ks++) {
            const int k = ks * 8;
            uint32_t a0 = __float_as_uint(Ps[q0w + gid    ][k + tig    ]);
            uint32_t a1 = __float_as_uint(Ps[q0w + gid + 8][k + tig    ]);
            uint32_t a2 = __float_as_uint(Ps[q0w + gid    ][k + tig + 4]);
            uint32_t a3 = __float_as_uint(Ps[q0w + gid + 8][k + tig + 4]);
#pragma unroll
            for (int nt = 0; nt < 8; nt++) {
                const int dn0 = nt * 8;
                uint32_t b0 = __float_as_uint(Vs[dn0 + gid][k + tig    ]);
                uint32_t b1 = __float_as_uint(Vs[dn0 + gid][k + tig + 4]);
                mma_tf32(o_acc[nt][0], o_acc[nt][1], o_acc[nt][2], o_acc[nt][3],
                         a0, a1, a2, a3, b0, b1);
            }
        }
        __syncthreads();   // before restaging Ks/Vs
    }

    // epilogue: normalize + direct scrambled-transposed store
    // reference scramble: b2 = bh%16, head2 = bh/16
    const int b2 = bh & 15, head2 = bh >> 4;
    const float inv0 = 1.0f / l0r;
    const float inv1 = 1.0f / l1r;
    float* base0 = g_aoT + ((size_t)b2 * HWDIM + n0 + q0w + gid    ) * CDIM + head2 * DH + 2 * tig;
    float* base1 = g_aoT + ((size_t)b2 * HWDIM + n0 + q0w + gid + 8) * CDIM + head2 * DH + 2 * tig;
#pragma unroll
    for (int nt = 0; nt < 8; nt++) {
        float2 w0, w1;
        w0.x = o_acc[nt][0] * inv0; w0.y = o_acc[nt][1] * inv0;
        w1.x = o_acc[nt][2] * inv1; w1.y = o_acc[nt][3] * inv1;
        *reinterpret_cast<float2*>(base0 + nt * 8) = w0;
        *reinterpret_cast<float2*>(base1 + nt * 8) = w1;
    }
}

// ============================================================
// launcher
// ============================================================
extern "C" void kernel_launch(void* const* d_in, const int* in_sizes, int n_in,
                              void* d_out, int out_size)
{
    const float* x      = (const float*)d_in[0];
    const float* gamma  = (const float*)d_in[1];
    const float* beta   = (const float*)d_in[2];
    const float* w_qkv  = (const float*)d_in[3];
    const float* b_qkv  = (const float*)d_in[4];
    const float* w_proj = (const float*)d_in[5];
    const float* b_proj = (const float*)d_in[6];
    float* out = (float*)d_out;

    cudaFuncSetAttribute(attn_kernel, cudaFuncAttributeMaxDynamicSharedMemorySize, ATTN_SMEM);

    // 1) GroupNorm (writes hT)
    groupnorm_kernel<<<BATCH * NGROUPS, 256>>>(x, gamma, beta);

    // 2) QKV GEMM (mma.sync tf32): per batch 1536 x 1024 x 512
    {
        dim3 grid(HWDIM / 128, C3 / 128, BATCH);
        gemm_mma<0><<<grid, 256>>>(w_qkv, b_qkv, nullptr, nullptr);
    }

    // 3) Attention (tensor-core flash, writes aoT scrambled)
    {
        dim3 grid(HWDIM / 64, BATCH * NH);
        attn_kernel<<<grid, 128, ATTN_SMEM>>>();
    }

    // 4) Proj GEMM (mma.sync tf32) + bias + residual
    {
        dim3 grid(HWDIM / 128, CDIM / 128, BATCH);
        gemm_mma<1><<<grid, 256>>>(w_proj, b_proj, x, out);
    }
}

// round 12
// speedup vs baseline: 5.9872x; 1.0158x over previous
#include <cuda_runtime.h>
#include <cstdint>
#include <math.h>

// ---------------- problem constants ----------------
#define BATCH   16
#define CDIM    512
#define HWDIM   1024            // H*W = 32*32
#define NGROUPS 32
#define CPG     (CDIM / NGROUPS)   // 16
#define NH      8
#define DH      64
#define C3      (3 * CDIM)          // 1536
#define EPSV    1e-5f
#define ATTN_SCALE 0.044194173824159216f   // C ** -0.5 (full dim, per reference)

// ---------------- scratch (device globals: alloc-free rule) ----------------
__device__ float g_hT [BATCH * HWDIM * CDIM];   // groupnorm out, transposed (B, HW, C)
__device__ float g_qkv[BATCH * C3   * HWDIM];   // qkv projection          (B, 3C, HW)
__device__ float g_aoT[BATCH * HWDIM * CDIM];   // attn out, transposed    (B, HW, C) [head-scrambled]

// ---------------- PTX helpers ----------------
__device__ __forceinline__ uint32_t smem_u32(const void* p) {
    uint32_t a;
    asm("{ .reg .u64 t; cvta.to.shared.u64 t, %1; cvt.u32.u64 %0, t; }" : "=r"(a) : "l"(p));
    return a;
}
__device__ __forceinline__ void cp16(uint32_t dst, const void* src) {
    asm volatile("cp.async.ca.shared.global [%0], [%1], 16;" :: "r"(dst), "l"(src));
}
#define CP_COMMIT() asm volatile("cp.async.commit_group;" ::: "memory")
#define CP_WAIT1()  asm volatile("cp.async.wait_group 1;" ::: "memory")
#define CP_WAIT0()  asm volatile("cp.async.wait_group 0;" ::: "memory")

// mma.sync m16n8k8 tf32 (family-generic, sm_80+): D = A(row) * B(col) + D
// fp32 operands fed raw: HW truncates to tf32 (cuBLAS TF32-mode semantics).
__device__ __forceinline__ void mma_tf32(float& c0, float& c1, float& c2, float& c3,
                                         uint32_t a0, uint32_t a1, uint32_t a2, uint32_t a3,
                                         uint32_t b0, uint32_t b1) {
    asm volatile(
        "mma.sync.aligned.m16n8k8.row.col.f32.tf32.tf32.f32 "
        "{%0,%1,%2,%3}, {%4,%5,%6,%7}, {%8,%9}, {%0,%1,%2,%3};\n"
        : "+f"(c0), "+f"(c1), "+f"(c2), "+f"(c3)
        : "r"(a0), "r"(a1), "r"(a2), "r"(a3), "r"(b0), "r"(b1));
}

// ============================================================
// 1) GroupNorm -> writes transposed g_hT[b][hw][c]
// ============================================================
__global__ __launch_bounds__(256)
void groupnorm_kernel(const float* __restrict__ x,
                      const float* __restrict__ gamma,
                      const float* __restrict__ beta)
{
    const int bg = blockIdx.x;
    const int b = bg / NGROUPS, g = bg % NGROUPS;
    const int t = threadIdx.x;
    const float* xp = x + (size_t)(b * CDIM + g * CPG) * HWDIM;

    float4 v[16];
    float s = 0.f, ss = 0.f;
#pragma unroll
    for (int i = 0; i < 16; i++) {
        v[i] = reinterpret_cast<const float4*>(xp)[i * 256 + t];
        s  += v[i].x + v[i].y + v[i].z + v[i].w;
        ss += v[i].x * v[i].x + v[i].y * v[i].y + v[i].z * v[i].z + v[i].w * v[i].w;
    }
#pragma unroll
    for (int m = 16; m > 0; m >>= 1) {
        s  += __shfl_xor_sync(0xffffffffu, s,  m);
        ss += __shfl_xor_sync(0xffffffffu, ss, m);
    }
    __shared__ float rs[8], rss[8];
    if ((t & 31) == 0) { rs[t >> 5] = s; rss[t >> 5] = ss; }
    __syncthreads();
    float tot = 0.f, tots = 0.f;
#pragma unroll
    for (int i = 0; i < 8; i++) { tot += rs[i]; tots += rss[i]; }

    const float invN = 1.0f / (float)(CPG * HWDIM);
    const float mean = tot * invN;
    const float var  = tots * invN - mean * mean;
    const float rstd = rsqrtf(var + EPSV);

    float ga[16], be[16];
#pragma unroll
    for (int i = 0; i < 16; i++) {
        ga[i] = gamma[g * CPG + i] * rstd;
        be[i] = beta[g * CPG + i];
    }
#pragma unroll
    for (int i = 0; i < 16; i++) {
        v[i].x = (v[i].x - mean) * ga[i] + be[i];
        v[i].y = (v[i].y - mean) * ga[i] + be[i];
        v[i].z = (v[i].z - mean) * ga[i] + be[i];
        v[i].w = (v[i].w - mean) * ga[i] + be[i];
    }
    float* hp = g_hT + ((size_t)b * HWDIM + 4 * t) * CDIM + g * CPG;
#pragma unroll
    for (int j = 0; j < 4; j++) {
        const float* c0 = (j == 0) ? &v[0].x : (j == 1) ? &v[0].y : (j == 2) ? &v[0].z : &v[0].w;
        float4 o0, o1, o2, o3;
        o0.x = c0[0*4];  o0.y = c0[1*4];  o0.z = c0[2*4];  o0.w = c0[3*4];
        o1.x = c0[4*4];  o1.y = c0[5*4];  o1.z = c0[6*4];  o1.w = c0[7*4];
        o2.x = c0[8*4];  o2.y = c0[9*4];  o2.z = c0[10*4]; o2.w = c0[11*4];
        o3.x = c0[12*4]; o3.y = c0[13*4]; o3.z = c0[14*4]; o3.w = c0[15*4];
        float* row = hp + (size_t)j * CDIM;
        reinterpret_cast<float4*>(row)[0] = o0;
        reinterpret_cast<float4*>(row)[1] = o1;
        reinterpret_cast<float4*>(row)[2] = o2;
        reinterpret_cast<float4*>(row)[3] = o3;
    }
}

// ============================================================
// 2/4) mma.sync tf32 GEMM with cp.async double-buffered pipeline.
//   out[b,m,n] = sum_c A[m,c]*Bsrc[b,n,c] (+bias,+resid)
//   CTA: 128m x 128n; k chunks of 32, 2-deep ping-pong smem buffers.
// ============================================================
#define LDA 36
#define GEMM_SMEM (2 * 2 * 128 * LDA * 4)   // 2 bufs x (A+B) x 128 x 36 floats = 73728 B

template <int MODE>
__global__ __launch_bounds__(256, 2)
void gemm_mma(const float* __restrict__ A,
              const float* __restrict__ bias,
              const float* __restrict__ resid,
              float* __restrict__ outp)
{
    constexpr int M = (MODE == 0) ? C3 : CDIM;
    extern __shared__ float smem[];
    float (*As)[128][LDA] = reinterpret_cast<float(*)[128][LDA]>(smem);                 // [buf][m][k]
    float (*Bs)[128][LDA] = reinterpret_cast<float(*)[128][LDA]>(smem + 2 * 128 * LDA); // [buf][n][k]

    const int b  = blockIdx.z;
    const int m0 = blockIdx.y * 128;
    const int n0 = blockIdx.x * 128;
    const float* Ag = A + (size_t)m0 * CDIM;
    const float* Bg = ((MODE == 0) ? g_hT : g_aoT) + ((size_t)b * HWDIM + n0) * CDIM;
    float* out = (MODE == 0) ? (float*)g_qkv : outp;

    const int t = threadIdx.x;
    const int wid = t >> 5, lane = t & 31;
    const int gid = lane >> 2, tig = lane & 3;
    const int wm = (wid & 1) * 64;
    const int wn = (wid >> 1) * 32;

    const int srow = t >> 3;            // staging: rows srow, srow+32, +64, +96
    const int scol = (t & 7) * 4;

    // stage chunk ch into buffer buf (1 cp.async group)
    auto stage = [&](int ch, int buf) {
        const int k0 = ch * 32;
#pragma unroll
        for (int it = 0; it < 4; it++) {
            const int r = srow + it * 32;
            cp16(smem_u32(&As[buf][r][scol]), Ag + (size_t)r * CDIM + k0 + scol);
            cp16(smem_u32(&Bs[buf][r][scol]), Bg + (size_t)r * CDIM + k0 + scol);
        }
        CP_COMMIT();
    };

    float acc[4][4][4] = {};

    stage(0, 0);
    stage(1, 1);

    for (int ch = 0; ch < 16; ch++) {
        const int buf = ch & 1;
        if (ch < 15) CP_WAIT1(); else CP_WAIT0();
        __syncthreads();

#pragma unroll
        for (int ks = 0; ks < 4; ks++) {
            const int k = ks * 8;
            uint32_t afr[4][4];
#pragma unroll
            for (int mt = 0; mt < 4; mt++) {
                const int mr = wm + mt * 16;
                afr[mt][0] = __float_as_uint(As[buf][mr + gid    ][k + tig    ]);
                afr[mt][1] = __float_as_uint(As[buf][mr + gid + 8][k + tig    ]);
                afr[mt][2] = __float_as_uint(As[buf][mr + gid    ][k + tig + 4]);
                afr[mt][3] = __float_as_uint(As[buf][mr + gid + 8][k + tig + 4]);
            }
            uint32_t bfr[4][2];
#pragma unroll
            for (int nt = 0; nt < 4; nt++) {
                const int nr = wn + nt * 8;
                bfr[nt][0] = __float_as_uint(Bs[buf][nr + gid][k + tig    ]);
                bfr[nt][1] = __float_as_uint(Bs[buf][nr + gid][k + tig + 4]);
            }
#pragma unroll
            for (int mt = 0; mt < 4; mt++)
#pragma unroll
                for (int nt = 0; nt < 4; nt++)
                    mma_tf32(acc[mt][nt][0], acc[mt][nt][1], acc[mt][nt][2], acc[mt][nt][3],
                             afr[mt][0], afr[mt][1], afr[mt][2], afr[mt][3],
                             bfr[nt][0], bfr[nt][1]);
        }
        __syncthreads();
        if (ch + 2 < 16) stage(ch + 2, buf);
    }

#pragma unroll
    for (int mt = 0; mt < 4; mt++) {
        const int r0 = m0 + wm + mt * 16 + gid;
        const int r1 = r0 + 8;
        const float bi0 = bias[r0], bi1 = bias[r1];
#pragma unroll
        for (int nt = 0; nt < 4; nt++) {
            const int n = n0 + wn + nt * 8 + 2 * tig;
            float2 o0, o1;
            o0.x = acc[mt][nt][0] + bi0; o0.y = acc[mt][nt][1] + bi0;
            o1.x = acc[mt][nt][2] + bi1; o1.y = acc[mt][nt][3] + bi1;
            const size_t off0 = ((size_t)b * M + r0) * HWDIM + n;
            const size_t off1 = ((size_t)b * M + r1) * HWDIM + n;
            if (MODE == 1) {
                const float2 x0 = *reinterpret_cast<const float2*>(resid + off0);
                const float2 x1 = *reinterpret_cast<const float2*>(resid + off1);
                o0.x += x0.x; o0.y += x0.y;
                o1.x += x1.x; o1.y += x1.y;
            }
            *reinterpret_cast<float2*>(out + off0) = o0;
            *reinterpret_cast<float2*>(out + off1) = o1;
        }
    }
}

// ============================================================
// 3) Flash attention on tensor cores, cp.async double-buffered K/V.
//    128 threads = 4 warps; warp w owns q rows [16w, 16w+16).
//    Smem: Qs[c][q], Ps[q][k], Ks[2][c][k], Vs[2][d][k].
// ============================================================
#define ASTR 68
#define ATTN_SMEM (6 * 64 * ASTR * 4)   // Qs + Ps + 2*(Ks+Vs) = 104448 B

__global__ __launch_bounds__(128)
void attn_kernel()
{
    extern __shared__ float sm[];
    float (*Qs)[ASTR]     = (float(*)[ASTR])(sm);                       // [c][q]
    float (*Ps)[ASTR]     = (float(*)[ASTR])(sm + 64 * ASTR);           // [q][k]
    float (*Ks)[64][ASTR] = (float(*)[64][ASTR])(sm + 2 * 64 * ASTR);   // [buf][c][k]
    float (*Vs)[64][ASTR] = (float(*)[64][ASTR])(sm + 4 * 64 * ASTR);   // [buf][d][k]

    const int qt = blockIdx.x;
    const int bh = blockIdx.y;
    const int b = bh >> 3, head = bh & 7;
    const int n0 = qt * 64;

    const float* qkv = g_qkv + (size_t)b * C3 * HWDIM;
    const float* Qg = qkv + (size_t)(head * 192)       * HWDIM;
    const float* Kg = qkv + (size_t)(head * 192 + 64)  * HWDIM;
    const float* Vg = qkv + (size_t)(head * 192 + 128) * HWDIM;

    const int t = threadIdx.x;
    const int wid = t >> 5, lane = t & 31;
    const int gid = lane >> 2, tig = lane & 3;
    const int q0w = wid * 16;

    const int scol = (t & 15) * 4;      // staging col
    const int srow = t >> 4;            // staging row base (8 rows apart)

    // stage K/V tile kt into buffer buf (1 cp.async group)
    auto stageKV = [&](int kt, int buf) {
        const int k0 = kt * 64;
#pragma unroll
        for (int p = 0; p < 8; p++) {
            const int row = srow + p * 8;
            cp16(smem_u32(&Ks[buf][row][scol]), Kg + (size_t)row * HWDIM + k0 + scol);
            cp16(smem_u32(&Vs[buf][row][scol]), Vg + (size_t)row * HWDIM + k0 + scol);
        }
        CP_COMMIT();
    };

    stageKV(0, 0);
    stageKV(1, 1);

    // stage Q (scaled) via regular loads
#pragma unroll
    for (int p = 0; p < 8; p++) {
        const int row = srow + p * 8;
        float4 qv = *reinterpret_cast<const float4*>(Qg + (size_t)row * HWDIM + n0 + scol);
        qv.x *= ATTN_SCALE; qv.y *= ATTN_SCALE; qv.z *= ATTN_SCALE; qv.w *= ATTN_SCALE;
        *reinterpret_cast<float4*>(&Qs[row][scol]) = qv;
    }

    float o_acc[8][4] = {};
    float m0r = -1e30f, m1r = -1e30f;
    float l0r = 0.f, l1r = 0.f;

    for (int kt = 0; kt < 16; kt++) {
        const int buf = kt & 1;
        if (kt < 15) CP_WAIT1(); else CP_WAIT0();
        __syncthreads();   // K/V[buf] visible to all; also covers Qs on kt=0

        // S = Q K^T
        float s_acc[8][4] = {};
#pragma unroll
        for (int ks = 0; ks < 8; ks++) {
            const int k = ks * 8;
            uint32_t a0 = __float_as_uint(Qs[k + tig    ][q0w + gid    ]);
            uint32_t a1 = __float_as_uint(Qs[k + tig    ][q0w + gid + 8]);
            uint32_t a2 = __float_as_uint(Qs[k + tig + 4][q0w + gid    ]);
            uint32_t a3 = __float_as_uint(Qs[k + tig + 4][q0w + gid + 8]);
#pragma unroll
            for (int nt = 0; nt < 8; nt++) {
                const int kn0 = nt * 8;
                uint32_t b0 = __float_as_uint(Ks[buf][k + tig    ][kn0 + gid]);
                uint32_t b1 = __float_as_uint(Ks[buf][k + tig + 4][kn0 + gid]);
                mma_tf32(s_acc[nt][0], s_acc[nt][1], s_acc[nt][2], s_acc[nt][3],
                         a0, a1, a2, a3, b0, b1);
            }
        }

        // online softmax on fragments
        float mx0 = -1e30f, mx1 = -1e30f;
#pragma unroll
        for (int nt = 0; nt < 8; nt++) {
            mx0 = fmaxf(mx0, fmaxf(s_acc[nt][0], s_acc[nt][1]));
            mx1 = fmaxf(mx1, fmaxf(s_acc[nt][2], s_acc[nt][3]));
        }
        mx0 = fmaxf(mx0, __shfl_xor_sync(0xffffffffu, mx0, 1));
        mx0 = fmaxf(mx0, __shfl_xor_sync(0xffffffffu, mx0, 2));
        mx1 = fmaxf(mx1, __shfl_xor_sync(0xffffffffu, mx1, 1));
        mx1 = fmaxf(mx1, __shfl_xor_sync(0xffffffffu, mx1, 2));

        const float nm0 = fmaxf(m0r, mx0);
        const float nm1 = fmaxf(m1r, mx1);
        const float al0 = __expf(m0r - nm0);
        const float al1 = __expf(m1r - nm1);
        m0r = nm0; m1r = nm1;

        float rl0 = 0.f, rl1 = 0.f;
#pragma unroll
        for (int nt = 0; nt < 8; nt++) {
            s_acc[nt][0] = __expf(s_acc[nt][0] - nm0);
            s_acc[nt][1] = __expf(s_acc[nt][1] - nm0);
            s_acc[nt][2] = __expf(s_acc[nt][2] - nm1);
            s_acc[nt][3] = __expf(s_acc[nt][3] - nm1);
            rl0 += s_acc[nt][0] + s_acc[nt][1];
            rl1 += s_acc[nt][2] + s_acc[nt][3];
        }
        rl0 += __shfl_xor_sync(0xffffffffu, rl0, 1);
        rl0 += __shfl_xor_sync(0xffffffffu, rl0, 2);
        rl1 += __shfl_xor_sync(0xffffffffu, rl1, 1);
        rl1 += __shfl_xor_sync(0xffffffffu, rl1, 2);
        l0r = l0r * al0 + rl0;
        l1r = l1r * al1 + rl1;

#pragma unroll
        for (int nt = 0; nt < 8; nt++) {
            o_acc[nt][0] *= al0; o_acc[nt][1] *= al0;
            o_acc[nt][2] *= al1; o_acc[nt][3] *= al1;
        }

        // P -> smem (per-warp rows)
#pragma unroll
        for (int nt = 0; nt < 8; nt++) {
            float2 p0, p1;
            p0.x = s_acc[nt][0]; p0.y = s_acc[nt][1];
            p1.x = s_acc[nt][2]; p1.y = s_acc[nt][3];
            *reinterpret_cast<float2*>(&Ps[q0w + gid    ][nt * 8 + 2 * tig]) = p0;
            *reinterpret_cast<float2*>(&Ps[q0w + gid + 8][nt * 8 + 2 * tig]) = p1;
        }
        __syncwarp();

        // O += P V
#pragma unroll
        for (int ks = 0; ks < 8; ks++) {
            const int k = ks * 8;
            uint32_t a0 = __float_as_uint(Ps[q0w + gid    ][k + tig    ]);
            uint32_t a1 = __float_as_uint(Ps[q0w + gid + 8][k + tig    ]);
            uint32_t a2 = __float_as_uint(Ps[q0w + gid    ][k + tig + 4]);
            uint32_t a3 = __float_as_uint(Ps[q0w + gid + 8][k + tig + 4]);
#pragma unroll
            for (int nt = 0; nt < 8; nt++) {
                const int dn0 = nt * 8;
                uint32_t b0 = __float_as_uint(Vs[buf][dn0 + gid][k + tig    ]);
                uint32_t b1 = __float_as_uint(Vs[buf][dn0 + gid][k + tig + 4]);
                mma_tf32(o_acc[nt][0], o_acc[nt][1], o_acc[nt][2], o_acc[nt][3],
                         a0, a1, a2, a3, b0, b1);
            }
        }
        __syncthreads();   // all reads of buf done before restaging into it
        if (kt + 2 < 16) stageKV(kt + 2, buf);
    }

    // epilogue: normalize + direct scrambled-transposed store
    const int b2 = bh & 15, head2 = bh >> 4;
    const float inv0 = 1.0f / l0r;
    const float inv1 = 1.0f / l1r;
    float* base0 = g_aoT + ((size_t)b2 * HWDIM + n0 + q0w + gid    ) * CDIM + head2 * DH + 2 * tig;
    float* base1 = g_aoT + ((size_t)b2 * HWDIM + n0 + q0w + gid + 8) * CDIM + head2 * DH + 2 * tig;
#pragma unroll
    for (int nt = 0; nt < 8; nt++) {
        float2 w0, w1;
        w0.x = o_acc[nt][0] * inv0; w0.y = o_acc[nt][1] * inv0;
        w1.x = o_acc[nt][2] * inv1; w1.y = o_acc[nt][3] * inv1;
        *reinterpret_cast<float2*>(base0 + nt * 8) = w0;
        *reinterpret_cast<float2*>(base1 + nt * 8) = w1;
    }
}

// ============================================================
// launcher
// ============================================================
extern "C" void kernel_launch(void* const* d_in, const int* in_sizes, int n_in,
                              void* d_out, int out_size)
{
    const float* x      = (const float*)d_in[0];
    const float* gamma  = (const float*)d_in[1];
    const float* beta   = (const float*)d_in[2];
    const float* w_qkv  = (const float*)d_in[3];
    const float* b_qkv  = (const float*)d_in[4];
    const float* w_proj = (const float*)d_in[5];
    const float* b_proj = (const float*)d_in[6];
    float* out = (float*)d_out;

    cudaFuncSetAttribute(attn_kernel,  cudaFuncAttributeMaxDynamicSharedMemorySize, ATTN_SMEM);
    cudaFuncSetAttribute(gemm_mma<0>,  cudaFuncAttributeMaxDynamicSharedMemorySize, GEMM_SMEM);
    cudaFuncSetAttribute(gemm_mma<1>,  cudaFuncAttributeMaxDynamicSharedMemorySize, GEMM_SMEM);

    // 1) GroupNorm (writes hT)
    groupnorm_kernel<<<BATCH * NGROUPS, 256>>>(x, gamma, beta);

    // 2) QKV GEMM (mma.sync tf32, cp.async pipeline)
    {
        dim3 grid(HWDIM / 128, C3 / 128, BATCH);
        gemm_mma<0><<<grid, 256, GEMM_SMEM>>>(w_qkv, b_qkv, nullptr, nullptr);
    }

    // 3) Attention (tensor-core flash, cp.async K/V pipeline)
    {
        dim3 grid(HWDIM / 64, BATCH * NH);
        attn_kernel<<<grid, 128, ATTN_SMEM>>>();
    }

    // 4) Proj GEMM (mma.sync tf32, cp.async pipeline) + bias + residual
    {
        dim3 grid(HWDIM / 128, CDIM / 128, BATCH);
        gemm_mma<1><<<grid, 256, GEMM_SMEM>>>(w_proj, b_proj, x, out);
    }
}

// round 16
// speedup vs baseline: 6.5032x; 1.0862x over previous
#include <cuda_runtime.h>
#include <cstdint>
#include <math.h>

// ---------------- problem constants ----------------
#define BATCH   16
#define CDIM    512
#define HWDIM   1024            // H*W = 32*32
#define NGROUPS 32
#define CPG     (CDIM / NGROUPS)   // 16
#define NH      8
#define DH      64
#define C3      (3 * CDIM)          // 1536
#define EPSV    1e-5f
#define ATTN_SCALE 0.044194173824159216f   // C ** -0.5 (full dim, per reference)

// ---------------- scratch (device globals: alloc-free rule) ----------------
__device__ float g_hT [BATCH * HWDIM * CDIM];   // groupnorm out, transposed (B, HW, C)
__device__ float g_qkv[BATCH * C3   * HWDIM];   // qkv projection          (B, 3C, HW)
__device__ float g_aoT[BATCH * HWDIM * CDIM];   // attn out, transposed    (B, HW, C) [head-scrambled]

// ---------------- PTX helpers ----------------
__device__ __forceinline__ uint32_t smem_u32(const void* p) {
    uint32_t a;
    asm("{ .reg .u64 t; cvta.to.shared.u64 t, %1; cvt.u32.u64 %0, t; }" : "=r"(a) : "l"(p));
    return a;
}
__device__ __forceinline__ void cp16(uint32_t dst, const void* src) {
    asm volatile("cp.async.ca.shared.global [%0], [%1], 16;" :: "r"(dst), "l"(src));
}
#define CP_COMMIT() asm volatile("cp.async.commit_group;" ::: "memory")
#define CP_WAIT1()  asm volatile("cp.async.wait_group 1;" ::: "memory")
#define CP_WAIT0()  asm volatile("cp.async.wait_group 0;" ::: "memory")

// mma.sync m16n8k8 tf32 (family-generic, sm_80+): D = A(row) * B(col) + D
// fp32 operands fed raw: HW truncates to tf32 (cuBLAS TF32-mode semantics).
__device__ __forceinline__ void mma_tf32(float& c0, float& c1, float& c2, float& c3,
                                         uint32_t a0, uint32_t a1, uint32_t a2, uint32_t a3,
                                         uint32_t b0, uint32_t b1) {
    asm volatile(
        "mma.sync.aligned.m16n8k8.row.col.f32.tf32.tf32.f32 "
        "{%0,%1,%2,%3}, {%4,%5,%6,%7}, {%8,%9}, {%0,%1,%2,%3};\n"
        : "+f"(c0), "+f"(c1), "+f"(c2), "+f"(c3)
        : "r"(a0), "r"(a1), "r"(a2), "r"(a3), "r"(b0), "r"(b1));
}

// ============================================================
// 1) GroupNorm -> writes transposed g_hT[b][hw][c]
// ============================================================
__global__ __launch_bounds__(256)
void groupnorm_kernel(const float* __restrict__ x,
                      const float* __restrict__ gamma,
                      const float* __restrict__ beta)
{
    const int bg = blockIdx.x;
    const int b = bg / NGROUPS, g = bg % NGROUPS;
    const int t = threadIdx.x;
    const float* xp = x + (size_t)(b * CDIM + g * CPG) * HWDIM;

    float4 v[16];
    float s = 0.f, ss = 0.f;
#pragma unroll
    for (int i = 0; i < 16; i++) {
        v[i] = reinterpret_cast<const float4*>(xp)[i * 256 + t];
        s  += v[i].x + v[i].y + v[i].z + v[i].w;
        ss += v[i].x * v[i].x + v[i].y * v[i].y + v[i].z * v[i].z + v[i].w * v[i].w;
    }
#pragma unroll
    for (int m = 16; m > 0; m >>= 1) {
        s  += __shfl_xor_sync(0xffffffffu, s,  m);
        ss += __shfl_xor_sync(0xffffffffu, ss, m);
    }
    __shared__ float rs[8], rss[8];
    if ((t & 31) == 0) { rs[t >> 5] = s; rss[t >> 5] = ss; }
    __syncthreads();
    float tot = 0.f, tots = 0.f;
#pragma unroll
    for (int i = 0; i < 8; i++) { tot += rs[i]; tots += rss[i]; }

    const float invN = 1.0f / (float)(CPG * HWDIM);
    const float mean = tot * invN;
    const float var  = tots * invN - mean * mean;
    const float rstd = rsqrtf(var + EPSV);

    float ga[16], be[16];
#pragma unroll
    for (int i = 0; i < 16; i++) {
        ga[i] = gamma[g * CPG + i] * rstd;
        be[i] = beta[g * CPG + i];
    }
#pragma unroll
    for (int i = 0; i < 16; i++) {
        v[i].x = (v[i].x - mean) * ga[i] + be[i];
        v[i].y = (v[i].y - mean) * ga[i] + be[i];
        v[i].z = (v[i].z - mean) * ga[i] + be[i];
        v[i].w = (v[i].w - mean) * ga[i] + be[i];
    }
    float* hp = g_hT + ((size_t)b * HWDIM + 4 * t) * CDIM + g * CPG;
#pragma unroll
    for (int j = 0; j < 4; j++) {
        const float* c0 = (j == 0) ? &v[0].x : (j == 1) ? &v[0].y : (j == 2) ? &v[0].z : &v[0].w;
        float4 o0, o1, o2, o3;
        o0.x = c0[0*4];  o0.y = c0[1*4];  o0.z = c0[2*4];  o0.w = c0[3*4];
        o1.x = c0[4*4];  o1.y = c0[5*4];  o1.z = c0[6*4];  o1.w = c0[7*4];
        o2.x = c0[8*4];  o2.y = c0[9*4];  o2.z = c0[10*4]; o2.w = c0[11*4];
        o3.x = c0[12*4]; o3.y = c0[13*4]; o3.z = c0[14*4]; o3.w = c0[15*4];
        float* row = hp + (size_t)j * CDIM;
        reinterpret_cast<float4*>(row)[0] = o0;
        reinterpret_cast<float4*>(row)[1] = o1;
        reinterpret_cast<float4*>(row)[2] = o2;
        reinterpret_cast<float4*>(row)[3] = o3;
    }
}

// ============================================================
// 2/4) mma.sync tf32 GEMM with cp.async double-buffered pipeline.
//   (unchanged from round 12, proven at 645.7us total)
// ============================================================
#define LDA 36
#define GEMM_SMEM (2 * 2 * 128 * LDA * 4)   // 73728 B

template <int MODE>
__global__ __launch_bounds__(256, 2)
void gemm_mma(const float* __restrict__ A,
              const float* __restrict__ bias,
              const float* __restrict__ resid,
              float* __restrict__ outp)
{
    constexpr int M = (MODE == 0) ? C3 : CDIM;
    extern __shared__ float smem[];
    float (*As)[128][LDA] = reinterpret_cast<float(*)[128][LDA]>(smem);
    float (*Bs)[128][LDA] = reinterpret_cast<float(*)[128][LDA]>(smem + 2 * 128 * LDA);

    const int b  = blockIdx.z;
    const int m0 = blockIdx.y * 128;
    const int n0 = blockIdx.x * 128;
    const float* Ag = A + (size_t)m0 * CDIM;
    const float* Bg = ((MODE == 0) ? g_hT : g_aoT) + ((size_t)b * HWDIM + n0) * CDIM;
    float* out = (MODE == 0) ? (float*)g_qkv : outp;

    const int t = threadIdx.x;
    const int wid = t >> 5, lane = t & 31;
    const int gid = lane >> 2, tig = lane & 3;
    const int wm = (wid & 1) * 64;
    const int wn = (wid >> 1) * 32;

    const int srow = t >> 3;
    const int scol = (t & 7) * 4;

    auto stage = [&](int ch, int buf) {
        const int k0 = ch * 32;
#pragma unroll
        for (int it = 0; it < 4; it++) {
            const int r = srow + it * 32;
            cp16(smem_u32(&As[buf][r][scol]), Ag + (size_t)r * CDIM + k0 + scol);
            cp16(smem_u32(&Bs[buf][r][scol]), Bg + (size_t)r * CDIM + k0 + scol);
        }
        CP_COMMIT();
    };

    float acc[4][4][4] = {};

    stage(0, 0);
    stage(1, 1);

    for (int ch = 0; ch < 16; ch++) {
        const int buf = ch & 1;
        if (ch < 15) CP_WAIT1(); else CP_WAIT0();
        __syncthreads();

#pragma unroll
        for (int ks = 0; ks < 4; ks++) {
            const int k = ks * 8;
            uint32_t afr[4][4];
#pragma unroll
            for (int mt = 0; mt < 4; mt++) {
                const int mr = wm + mt * 16;
                afr[mt][0] = __float_as_uint(As[buf][mr + gid    ][k + tig    ]);
                afr[mt][1] = __float_as_uint(As[buf][mr + gid + 8][k + tig    ]);
                afr[mt][2] = __float_as_uint(As[buf][mr + gid    ][k + tig + 4]);
                afr[mt][3] = __float_as_uint(As[buf][mr + gid + 8][k + tig + 4]);
            }
            uint32_t bfr[4][2];
#pragma unroll
            for (int nt = 0; nt < 4; nt++) {
                const int nr = wn + nt * 8;
                bfr[nt][0] = __float_as_uint(Bs[buf][nr + gid][k + tig    ]);
                bfr[nt][1] = __float_as_uint(Bs[buf][nr + gid][k + tig + 4]);
            }
#pragma unroll
            for (int mt = 0; mt < 4; mt++)
#pragma unroll
                for (int nt = 0; nt < 4; nt++)
                    mma_tf32(acc[mt][nt][0], acc[mt][nt][1], acc[mt][nt][2], acc[mt][nt][3],
                             afr[mt][0], afr[mt][1], afr[mt][2], afr[mt][3],
                             bfr[nt][0], bfr[nt][1]);
        }
        __syncthreads();
        if (ch + 2 < 16) stage(ch + 2, buf);
    }

#pragma unroll
    for (int mt = 0; mt < 4; mt++) {
        const int r0 = m0 + wm + mt * 16 + gid;
        const int r1 = r0 + 8;
        const float bi0 = bias[r0], bi1 = bias[r1];
#pragma unroll
        for (int nt = 0; nt < 4; nt++) {
            const int n = n0 + wn + nt * 8 + 2 * tig;
            float2 o0, o1;
            o0.x = acc[mt][nt][0] + bi0; o0.y = acc[mt][nt][1] + bi0;
            o1.x = acc[mt][nt][2] + bi1; o1.y = acc[mt][nt][3] + bi1;
            const size_t off0 = ((size_t)b * M + r0) * HWDIM + n;
            const size_t off1 = ((size_t)b * M + r1) * HWDIM + n;
            if (MODE == 1) {
                const float2 x0 = *reinterpret_cast<const float2*>(resid + off0);
                const float2 x1 = *reinterpret_cast<const float2*>(resid + off1);
                o0.x += x0.x; o0.y += x0.y;
                o1.x += x1.x; o1.y += x1.y;
            }
            *reinterpret_cast<float2*>(out + off0) = o0;
            *reinterpret_cast<float2*>(out + off1) = o1;
        }
    }
}

// ============================================================
// 3) Flash attention on tensor cores, v3:
//    - Q fragments resident in registers (loaded once via smem stage)
//    - single-buffered K/V via cp.async  -> smem 52 KB (natural 4 CTAs/SM
//      when regs <= 128; no forced min-blocks hint)
//    128 threads = 4 warps; warp w owns q rows [16w, 16w+16).
//    Smem: Ps[64][ASTR] (Q-stage, then P), Ks[64][ASTR], Vs[64][ASTR].
// ============================================================
#define ASTR 68
#define ATTN_SMEM (3 * 64 * ASTR * 4)   // 52224 B

__global__ void __launch_bounds__(128) attn_kernel()
{
    extern __shared__ float sm[];
    float (*Ps)[ASTR] = (float(*)[ASTR])(sm);                 // [c][q] stage, then [q][k]
    float (*Ks)[ASTR] = (float(*)[ASTR])(sm + 64 * ASTR);     // [c][k]
    float (*Vs)[ASTR] = (float(*)[ASTR])(sm + 2 * 64 * ASTR); // [d][k]

    const int qt = blockIdx.x;
    const int bh = blockIdx.y;
    const int b = bh >> 3, head = bh & 7;
    const int n0 = qt * 64;

    const float* qkv = g_qkv + (size_t)b * C3 * HWDIM;
    const float* Qg = qkv + (size_t)(head * 192)       * HWDIM;
    const float* Kg = qkv + (size_t)(head * 192 + 64)  * HWDIM;
    const float* Vg = qkv + (size_t)(head * 192 + 128) * HWDIM;

    const int t = threadIdx.x;
    const int wid = t >> 5, lane = t & 31;
    const int gid = lane >> 2, tig = lane & 3;
    const int q0w = wid * 16;

    const int scol = (t & 15) * 4;
    const int srow = t >> 4;

    // ---- stage Q (scaled) into Ps[c][q], then lift fragments to registers ----
#pragma unroll
    for (int p = 0; p < 8; p++) {
        const int row = srow + p * 8;
        float4 qv = *reinterpret_cast<const float4*>(Qg + (size_t)row * HWDIM + n0 + scol);
        qv.x *= ATTN_SCALE; qv.y *= ATTN_SCALE; qv.z *= ATTN_SCALE; qv.w *= ATTN_SCALE;
        *reinterpret_cast<float4*>(&Ps[row][scol]) = qv;
    }
    __syncthreads();
    uint32_t qf[8][4];
#pragma unroll
    for (int ks = 0; ks < 8; ks++) {
        const int k = ks * 8;
        qf[ks][0] = __float_as_uint(Ps[k + tig    ][q0w + gid    ]);
        qf[ks][1] = __float_as_uint(Ps[k + tig    ][q0w + gid + 8]);
        qf[ks][2] = __float_as_uint(Ps[k + tig + 4][q0w + gid    ]);
        qf[ks][3] = __float_as_uint(Ps[k + tig + 4][q0w + gid + 8]);
    }
    __syncthreads();   // Ps free for P use

    float o_acc[8][4] = {};
    float m0r = -1e30f, m1r = -1e30f;
    float l0r = 0.f, l1r = 0.f;

    for (int kt = 0; kt < 16; kt++) {
        const int k0 = kt * 64;
        // stage K/V tile (single buffer, cp.async)
#pragma unroll
        for (int p = 0; p < 8; p++) {
            const int row = srow + p * 8;
            cp16(smem_u32(&Ks[row][scol]), Kg + (size_t)row * HWDIM + k0 + scol);
            cp16(smem_u32(&Vs[row][scol]), Vg + (size_t)row * HWDIM + k0 + scol);
        }
        CP_COMMIT();
        CP_WAIT0();
        __syncthreads();

        // S = Q K^T (Q from registers)
        float s_acc[8][4] = {};
#pragma unroll
        for (int ks = 0; ks < 8; ks++) {
            const int k = ks * 8;
#pragma unroll
            for (int nt = 0; nt < 8; nt++) {
                const int kn0 = nt * 8;
                uint32_t b0 = __float_as_uint(Ks[k + tig    ][kn0 + gid]);
                uint32_t b1 = __float_as_uint(Ks[k + tig + 4][kn0 + gid]);
                mma_tf32(s_acc[nt][0], s_acc[nt][1], s_acc[nt][2], s_acc[nt][3],
                         qf[ks][0], qf[ks][1], qf[ks][2], qf[ks][3], b0, b1);
            }
        }

        // online softmax on fragments
        float mx0 = -1e30f, mx1 = -1e30f;
#pragma unroll
        for (int nt = 0; nt < 8; nt++) {
            mx0 = fmaxf(mx0, fmaxf(s_acc[nt][0], s_acc[nt][1]));
            mx1 = fmaxf(mx1, fmaxf(s_acc[nt][2], s_acc[nt][3]));
        }
        mx0 = fmaxf(mx0, __shfl_xor_sync(0xffffffffu, mx0, 1));
        mx0 = fmaxf(mx0, __shfl_xor_sync(0xffffffffu, mx0, 2));
        mx1 = fmaxf(mx1, __shfl_xor_sync(0xffffffffu, mx1, 1));
        mx1 = fmaxf(mx1, __shfl_xor_sync(0xffffffffu, mx1, 2));

        const float nm0 = fmaxf(m0r, mx0);
        const float nm1 = fmaxf(m1r, mx1);
        const float al0 = __expf(m0r - nm0);
        const float al1 = __expf(m1r - nm1);
        m0r = nm0; m1r = nm1;

        float rl0 = 0.f, rl1 = 0.f;
#pragma unroll
        for (int nt = 0; nt < 8; nt++) {
            s_acc[nt][0] = __expf(s_acc[nt][0] - nm0);
            s_acc[nt][1] = __expf(s_acc[nt][1] - nm0);
            s_acc[nt][2] = __expf(s_acc[nt][2] - nm1);
            s_acc[nt][3] = __expf(s_acc[nt][3] - nm1);
            rl0 += s_acc[nt][0] + s_acc[nt][1];
            rl1 += s_acc[nt][2] + s_acc[nt][3];
        }
        rl0 += __shfl_xor_sync(0xffffffffu, rl0, 1);
        rl0 += __shfl_xor_sync(0xffffffffu, rl0, 2);
        rl1 += __shfl_xor_sync(0xffffffffu, rl1, 1);
        rl1 += __shfl_xor_sync(0xffffffffu, rl1, 2);
        l0r = l0r * al0 + rl0;
        l1r = l1r * al1 + rl1;

#pragma unroll
        for (int nt = 0; nt < 8; nt++) {
            o_acc[nt][0] *= al0; o_acc[nt][1] *= al0;
            o_acc[nt][2] *= al1; o_acc[nt][3] *= al1;
        }

        // P -> smem (per-warp rows)
#pragma unroll
        for (int nt = 0; nt < 8; nt++) {
            float2 p0, p1;
            p0.x = s_acc[nt][0]; p0.y = s_acc[nt][1];
            p1.x = s_acc[nt][2]; p1.y = s_acc[nt][3];
            *reinterpret_cast<float2*>(&Ps[q0w + gid    ][nt * 8 + 2 * tig]) = p0;
            *reinterpret_cast<float2*>(&Ps[q0w + gid + 8][nt * 8 + 2 * tig]) = p1;
        }
        __syncwarp();

        // O += P V
#pragma unroll
        for (int ks = 0; ks < 8; ks++) {
            const int k = ks * 8;
            uint32_t a0 = __float_as_uint(Ps[q0w + gid    ][k + tig    ]);
            uint32_t a1 = __float_as_uint(Ps[q0w + gid + 8][k + tig    ]);
            uint32_t a2 = __float_as_uint(Ps[q0w + gid    ][k + tig + 4]);
            uint32_t a3 = __float_as_uint(Ps[q0w + gid + 8][k + tig + 4]);
#pragma unroll
            for (int nt = 0; nt < 8; nt++) {
                const int dn0 = nt * 8;
                uint32_t b0 = __float_as_uint(Vs[dn0 + gid][k + tig    ]);
                uint32_t b1 = __float_as_uint(Vs[dn0 + gid][k + tig + 4]);
                mma_tf32(o_acc[nt][0], o_acc[nt][1], o_acc[nt][2], o_acc[nt][3],
                         a0, a1, a2, a3, b0, b1);
            }
        }
        __syncthreads();   // all reads done before restaging Ks/Vs
    }

    // epilogue: normalize + direct scrambled-transposed store
    const int b2 = bh & 15, head2 = bh >> 4;
    const float inv0 = 1.0f / l0r;
    const float inv1 = 1.0f / l1r;
    float* base0 = g_aoT + ((size_t)b2 * HWDIM + n0 + q0w + gid    ) * CDIM + head2 * DH + 2 * tig;
    float* base1 = g_aoT + ((size_t)b2 * HWDIM + n0 + q0w + gid + 8) * CDIM + head2 * DH + 2 * tig;
#pragma unroll
    for (int nt = 0; nt < 8; nt++) {
        float2 w0, w1;
        w0.x = o_acc[nt][0] * inv0; w0.y = o_acc[nt][1] * inv0;
        w1.x = o_acc[nt][2] * inv1; w1.y = o_acc[nt][3] * inv1;
        *reinterpret_cast<float2*>(base0 + nt * 8) = w0;
        *reinterpret_cast<float2*>(base1 + nt * 8) = w1;
    }
}

// ============================================================
// launcher
// ============================================================
extern "C" void kernel_launch(void* const* d_in, const int* in_sizes, int n_in,
                              void* d_out, int out_size)
{
    const float* x      = (const float*)d_in[0];
    const float* gamma  = (const float*)d_in[1];
    const float* beta   = (const float*)d_in[2];
    const float* w_qkv  = (const float*)d_in[3];
    const float* b_qkv  = (const float*)d_in[4];
    const float* w_proj = (const float*)d_in[5];
    const float* b_proj = (const float*)d_in[6];
    float* out = (float*)d_out;

    cudaFuncSetAttribute(attn_kernel,  cudaFuncAttributeMaxDynamicSharedMemorySize, ATTN_SMEM);
    cudaFuncSetAttribute(gemm_mma<0>,  cudaFuncAttributeMaxDynamicSharedMemorySize, GEMM_SMEM);
    cudaFuncSetAttribute(gemm_mma<1>,  cudaFuncAttributeMaxDynamicSharedMemorySize, GEMM_SMEM);

    // 1) GroupNorm (writes hT)
    groupnorm_kernel<<<BATCH * NGROUPS, 256>>>(x, gamma, beta);

    // 2) QKV GEMM (mma.sync tf32, cp.async pipeline)
    {
        dim3 grid(HWDIM / 128, C3 / 128, BATCH);
        gemm_mma<0><<<grid, 256, GEMM_SMEM>>>(w_qkv, b_qkv, nullptr, nullptr);
    }

    // 3) Attention (tensor-core flash v3: Q-in-regs, single-buffer K/V)
    {
        dim3 grid(HWDIM / 64, BATCH * NH);
        attn_kernel<<<grid, 128, ATTN_SMEM>>>();
    }

    // 4) Proj GEMM (mma.sync tf32, cp.async pipeline) + bias + residual
    {
        dim3 grid(HWDIM / 128, CDIM / 128, BATCH);
        gemm_mma<1><<<grid, 256, GEMM_SMEM>>>(w_proj, b_proj, x, out);
    }
}